// round 6
// baseline (speedup 1.0000x reference)
#include <cuda_runtime.h>
#include <cstdint>
#include <cstddef>

// Problem constants
#define TT   512
#define BSZ  64
#define IC_  512
#define HC_  512
#define ZC_  2048
#define MR   (TT*BSZ)

#define RK_CTAS 128
#define RK_THR  256

typedef unsigned long long ull;

// ---------------------------------------------------------------------------
// Static device scratch (no cudaMalloc allowed)
// ---------------------------------------------------------------------------
__device__ float g_z[(size_t)MR * ZC_];        // 256 MB: x-projection (+bias), [m][2048]
__device__ float g_hseq[(size_t)MR * HC_];     // 64 MB: layer-0 h sequence [m][512]
__device__ float g_hbuf[2][HC_ * BSZ];         // double-buffered h, TRANSPOSED [j][b]
__device__ int   g_flags[RK_CTAS];             // per-CTA monotonic step counters

// ---------------------------------------------------------------------------
// f32x2 helpers (Blackwell packed fp32 FMA — SASS FFMA2)
// ---------------------------------------------------------------------------
__device__ __forceinline__ ull pack2(float x, float y) {
    ull r; asm("mov.b64 %0, {%1, %2};" : "=l"(r) : "f"(x), "f"(y)); return r;
}
__device__ __forceinline__ void unpack2(ull v, float& x, float& y) {
    asm("mov.b64 {%0, %1}, %2;" : "=f"(x), "=f"(y) : "l"(v));
}
__device__ __forceinline__ void ffma2(ull& d, ull a, ull b) {
    asm("fma.rn.f32x2 %0, %1, %2, %0;" : "+l"(d) : "l"(a), "l"(b));
}

__device__ __forceinline__ int ldacq(const int* p) {
    int v;
    asm volatile("ld.global.acquire.gpu.b32 %0, [%1];" : "=r"(v) : "l"(p) : "memory");
    return v;
}
__device__ __forceinline__ void strel(int* p, int v) {
    asm volatile("st.global.release.gpu.b32 [%0], %1;" :: "l"(p), "r"(v) : "memory");
}

__device__ __forceinline__ float sigf(float x) { return 1.0f / (1.0f + __expf(-x)); }
__device__ __forceinline__ float tanh_fast(float x) {
    float ax = fabsf(x);
    float e = __expf(-2.0f * ax);
    float r = (1.0f - e) / (1.0f + e);
    return copysignf(r, x);
}

// ---------------------------------------------------------------------------
// Phase 1: Z = A @ W[0:512,:] + bias, fp32 via packed FFMA2 (R4 layout),
// with 2-stage register prefetch of global tiles.
// Tile M=128,N=128,BK=16, 256 threads, per-thread 8x8 (32 FFMA2).
// ---------------------------------------------------------------------------
#define AS_STRIDE 264   // floats per k-row (256 dup'd data + 8 pad)
#define BS_STRIDE 136   // floats per k-row (128 data + 8 pad)

__global__ __launch_bounds__(256) void sgemm_bias(
        const float* __restrict__ A,       // [32768, 512] row-major
        const float* __restrict__ W,       // rows 0..511 of [., 2048]
        const float* __restrict__ bias,    // [2048]
        float* __restrict__ Z) {           // [32768, 2048]
    __shared__ float As2[16 * AS_STRIDE];
    __shared__ float Bs[16 * BS_STRIDE];

    const int tid = threadIdx.x;
    const int m0 = blockIdx.y * 128;
    const int n0 = blockIdx.x * 128;
    const int tx = tid & 15;        // n quad
    const int ty = tid >> 4;        // m quad

    ull acc[8][4];
#pragma unroll
    for (int i = 0; i < 8; i++)
#pragma unroll
        for (int j = 0; j < 4; j++) acc[i][j] = 0ull;

    const int ar = tid >> 2, ac4 = tid & 3;     // A staging
    const int br = tid >> 5, bc4 = tid & 31;    // B staging

    // Prologue prefetch of k0=0 tile
    float4 aPf[2], bPf[2];
#pragma unroll
    for (int p = 0; p < 2; p++)
        aPf[p] = *(const float4*)(A + (size_t)(m0 + ar + p * 64) * 512 + ac4 * 4);
#pragma unroll
    for (int p = 0; p < 2; p++)
        bPf[p] = *(const float4*)(W + (size_t)(br + p * 8) * ZC_ + n0 + bc4 * 4);

    for (int k0 = 0; k0 < 512; k0 += 16) {
        // Stage registers -> smem (A duplicated)
#pragma unroll
        for (int p = 0; p < 2; p++) {
            int r = ar + p * 64;
            const float* vf = (const float*)&aPf[p];
#pragma unroll
            for (int q = 0; q < 4; q++) {
                As2[(ac4 * 4 + q) * AS_STRIDE + 2 * r]     = vf[q];
                As2[(ac4 * 4 + q) * AS_STRIDE + 2 * r + 1] = vf[q];
            }
        }
#pragma unroll
        for (int p = 0; p < 2; p++)
            *(float4*)&Bs[(br + p * 8) * BS_STRIDE + bc4 * 4] = bPf[p];
        __syncthreads();

        // Prefetch next tile (overlapped with compute)
        if (k0 + 16 < 512) {
#pragma unroll
            for (int p = 0; p < 2; p++)
                aPf[p] = *(const float4*)(A + (size_t)(m0 + ar + p * 64) * 512 + k0 + 16 + ac4 * 4);
#pragma unroll
            for (int p = 0; p < 2; p++)
                bPf[p] = *(const float4*)(W + (size_t)(k0 + 16 + br + p * 8) * ZC_ + n0 + bc4 * 4);
        }

#pragma unroll
        for (int kk = 0; kk < 16; kk++) {
            ull a[8], b[4];
            {
                const ulonglong2* ap = (const ulonglong2*)&As2[kk * AS_STRIDE + 8 * ty];
                ulonglong2 a01 = ap[0], a23 = ap[1];
                a[0] = a01.x; a[1] = a01.y; a[2] = a23.x; a[3] = a23.y;
                const ulonglong2* ap2 = (const ulonglong2*)&As2[kk * AS_STRIDE + 128 + 8 * ty];
                ulonglong2 a45 = ap2[0], a67 = ap2[1];
                a[4] = a45.x; a[5] = a45.y; a[6] = a67.x; a[7] = a67.y;
            }
            {
                ulonglong2 b01 = *(const ulonglong2*)&Bs[kk * BS_STRIDE + 4 * tx];
                ulonglong2 b23 = *(const ulonglong2*)&Bs[kk * BS_STRIDE + 64 + 4 * tx];
                b[0] = b01.x; b[1] = b01.y; b[2] = b23.x; b[3] = b23.y;
            }
#pragma unroll
            for (int i = 0; i < 8; i++)
#pragma unroll
                for (int j = 0; j < 4; j++)
                    ffma2(acc[i][j], a[i], b[j]);
        }
        __syncthreads();
    }

    // Epilogue: coalesced STG.128, bias added
    float4 bv0 = *(const float4*)(bias + n0 + 4 * tx);
    float4 bv1 = *(const float4*)(bias + n0 + 64 + 4 * tx);
#pragma unroll
    for (int i = 0; i < 8; i++) {
        int m = m0 + ((i < 4) ? (ty * 4 + i) : (64 + ty * 4 + (i - 4)));
        float x0, x1, x2, x3;
        unpack2(acc[i][0], x0, x1);
        unpack2(acc[i][1], x2, x3);
        float4 o0 = make_float4(x0 + bv0.x, x1 + bv0.y, x2 + bv0.z, x3 + bv0.w);
        *(float4*)(Z + (size_t)m * ZC_ + n0 + 4 * tx) = o0;
        unpack2(acc[i][2], x0, x1);
        unpack2(acc[i][3], x2, x3);
        float4 o1 = make_float4(x0 + bv1.x, x1 + bv1.y, x2 + bv1.z, x3 + bv1.w);
        *(float4*)(Z + (size_t)m * ZC_ + n0 + 64 + 4 * tx) = o1;
    }
}

// ---------------------------------------------------------------------------
// Phase 2: persistent recurrence, flag-based distributed barrier.
// 128 CTAs x 256 threads. CTA owns 4 h-columns. Warp w: kq=w>>1, bh=w&1.
// Inner loop (R4 style): per kk 1 coalesced LDG.cg (h), 4 broadcast LDS.128 (w),
// 8 FFMA2. Cross-warp k-reduction via smem; gating over all 256 threads.
// Sync: per-CTA monotonic flag, st.release publish, 128-thread parallel
// ld.acquire polling. No atomics, no nanosleep, no generation reset.
// ---------------------------------------------------------------------------
__global__ __launch_bounds__(RK_THR, 1) void lstm_rec(
        const float* __restrict__ Wh,     // [512, 2048] recurrent rows of W
        const float* __restrict__ h0l,    // [512]
        const float* __restrict__ c0l,    // [512]
        float* __restrict__ hseq,         // [T*BS*HC], layout [m][512]
        float* __restrict__ hs_out,       // [BS*HC]
        float* __restrict__ cs_out) {     // [BS*HC]
    __shared__ float Wsm[HC_ * 16];       // 32 KB: [k][c*4+g]
    __shared__ ull  Rsm[8 * 4 * 64];      // 16 KB: [(idx*4+kq)*64 + b]

    const int tid  = threadIdx.x;
    const int cid  = blockIdx.x;
    const int j0   = cid << 2;
    const int wid  = tid >> 5, lane = tid & 31;
    const int kq   = wid >> 1, bh = wid & 1;
    const int kbase = kq << 7;
    const int bb   = (bh << 5) + lane;    // batch row for GEMM

    // Weights: Wsm[k*16 + c*4 + g] = Wh[k][g*512 + j0 + c]
    for (int idx = tid; idx < HC_ * 16; idx += RK_THR) {
        int k = idx >> 4, c = (idx >> 2) & 3, g = idx & 3;
        Wsm[idx] = Wh[(size_t)k * ZC_ + (size_t)g * HC_ + j0 + c];
    }

    // All flags are equal at kernel entry (monotonic across launches/replays).
    const int base = g_flags[cid];

    // Finalizer identity: thread -> (col fc, batch fb)
    const int fc = tid >> 6;
    const int fb = tid & 63;
    const int fj = j0 + fc;
    float cstate = c0l[fj];
    float hlast  = h0l[fj];
    __stcg(&g_hbuf[0][fj * BSZ + fb], hlast);
    __syncthreads();
    if (tid == 0) strel(&g_flags[cid], base + 1);

    for (int t = 0; t < TT; t++) {
        const int want = base + 1 + t;

        // z prefetch (issued before wait; consumed after reduction)
        const float* zr = g_z + (size_t)(t * BSZ + fb) * ZC_ + fj;
        float z0 = __ldcg(zr);
        float z1 = __ldcg(zr + HC_);
        float z2 = __ldcg(zr + 2 * HC_);
        float z3 = __ldcg(zr + 3 * HC_);

        // Wait for all producers of h_t (parallel flag poll)
        if (tid < RK_CTAS) {
            while (ldacq(&g_flags[tid]) < want) {}
        }
        __syncthreads();

        const float* hb = g_hbuf[t & 1];
        ull acc[4][2];
#pragma unroll
        for (int c = 0; c < 4; c++) { acc[c][0] = 0ull; acc[c][1] = 0ull; }

#pragma unroll 8
        for (int kk = 0; kk < 128; kk++) {
            int k = kbase + kk;
            float hv = __ldcg(hb + k * BSZ + bb);
            ull h2 = pack2(hv, hv);
            const float* wrow = Wsm + k * 16;
#pragma unroll
            for (int c = 0; c < 4; c++) {
                ulonglong2 w2 = *(const ulonglong2*)(wrow + c * 4);
                ffma2(acc[c][0], h2, w2.x);
                ffma2(acc[c][1], h2, w2.y);
            }
        }

        // Cross-warp k-reduction via smem (conflict-free layout)
#pragma unroll
        for (int c = 0; c < 4; c++)
#pragma unroll
            for (int p = 0; p < 2; p++)
                Rsm[((c * 2 + p) * 4 + kq) * 64 + bb] = acc[c][p];
        __syncthreads();

        float f = z0, i = z1, o = z2, g = z3;
#pragma unroll
        for (int q = 0; q < 4; q++) {
            float a0, a1, a2, a3;
            unpack2(Rsm[((fc * 2 + 0) * 4 + q) * 64 + fb], a0, a1);
            unpack2(Rsm[((fc * 2 + 1) * 4 + q) * 64 + fb], a2, a3);
            f += a0; i += a1; o += a2; g += a3;
        }
        f = sigf(f + 1.0f);           // FORGET_BIAS
        i = sigf(i);
        o = sigf(o);
        g = tanh_fast(g);
        cstate = cstate * f + g * i;
        hlast = o * tanh_fast(cstate);

        // Publish h_{t+1} ASAP; hseq store after the flag (not cross-CTA)
        __stcg(&g_hbuf[(t + 1) & 1][fj * BSZ + fb], hlast);
        __syncthreads();
        if (tid == 0) strel(&g_flags[cid], want + 1);
        hseq[(size_t)(t * BSZ + fb) * HC_ + fj] = hlast;
    }

    hs_out[fb * HC_ + fj] = hlast;
    cs_out[fb * HC_ + fj] = cstate;
}

// ---------------------------------------------------------------------------
// Launch: sgemm(L0) -> rec(L0) -> sgemm(L1) -> rec(L1 -> d_out)
// ---------------------------------------------------------------------------
extern "C" void kernel_launch(void* const* d_in, const int* in_sizes, int n_in,
                              void* d_out, int out_size) {
    const float* x  = (const float*)d_in[0];
    const float* W0 = (const float*)d_in[1];
    const float* b0 = (const float*)d_in[2];
    const float* W1 = (const float*)d_in[3];
    const float* b1 = (const float*)d_in[4];
    const float* h0 = (const float*)d_in[5];
    const float* c0 = (const float*)d_in[6];

    float* out = (float*)d_out;                      // [T, BS, HC]
    float* hs  = out + (size_t)TT * BSZ * HC_;       // [L, BS, HC]
    float* cs  = hs + (size_t)2 * BSZ * HC_;         // [L, BS, HC]

    float* zptr = nullptr;
    float* hseq0 = nullptr;
    cudaGetSymbolAddress((void**)&zptr, g_z);
    cudaGetSymbolAddress((void**)&hseq0, g_hseq);

    dim3 ggrid(ZC_ / 128, MR / 128);

    // Layer 0
    sgemm_bias<<<ggrid, 256>>>(x, W0, b0, zptr);
    lstm_rec<<<RK_CTAS, RK_THR>>>(W0 + (size_t)IC_ * ZC_, h0, c0,
                                  hseq0, hs, cs);
    // Layer 1
    sgemm_bias<<<ggrid, 256>>>(hseq0, W1, b1, zptr);
    lstm_rec<<<RK_CTAS, RK_THR>>>(W1 + (size_t)HC_ * ZC_, h0 + HC_, c0 + HC_,
                                  out, hs + BSZ * HC_, cs + BSZ * HC_);
}

// round 7
// speedup vs baseline: 1.4642x; 1.4642x over previous
#include <cuda_runtime.h>
#include <cstdint>
#include <cstddef>

// Problem constants
#define TT   512
#define BSZ  64
#define IC_  512
#define HC_  512
#define ZC_  2048
#define MR   (TT*BSZ)

#define RK_CTAS 128
#define RK_THR  512

typedef unsigned long long ull;

// ---------------------------------------------------------------------------
// Static device scratch (no cudaMalloc allowed)
// ---------------------------------------------------------------------------
__device__ float g_z[(size_t)MR * ZC_];        // 256 MB: x-projection (+bias), [m][2048]
__device__ float g_hseq[(size_t)MR * HC_];     // 64 MB: layer-0 h sequence [m][512]
__device__ float g_hbuf[2][HC_ * BSZ];         // double-buffered h, TRANSPOSED [j][b]
__device__ unsigned g_barcnt = 0;
__device__ volatile unsigned g_bargen = 0;

// ---------------------------------------------------------------------------
// f32x2 helpers (Blackwell packed fp32 — SASS FFMA2 / FADD2)
// ---------------------------------------------------------------------------
__device__ __forceinline__ ull pack2(float x, float y) {
    ull r; asm("mov.b64 %0, {%1, %2};" : "=l"(r) : "f"(x), "f"(y)); return r;
}
__device__ __forceinline__ void unpack2(ull v, float& x, float& y) {
    asm("mov.b64 {%0, %1}, %2;" : "=f"(x), "=f"(y) : "l"(v));
}
__device__ __forceinline__ void ffma2(ull& d, ull a, ull b) {
    asm("fma.rn.f32x2 %0, %1, %2, %0;" : "+l"(d) : "l"(a), "l"(b));
}
__device__ __forceinline__ void fadd2(ull& d, ull a) {
    asm("add.rn.f32x2 %0, %0, %1;" : "+l"(d) : "l"(a));
}

__device__ __forceinline__ float sigf(float x) { return 1.0f / (1.0f + __expf(-x)); }
__device__ __forceinline__ float tanh_fast(float x) {
    float ax = fabsf(x);
    float e = __expf(-2.0f * ax);
    float r = (1.0f - e) / (1.0f + e);
    return copysignf(r, x);
}

// Central-atomic grid barrier (R4-proven; 128 CTAs co-resident, no sleep)
__device__ __forceinline__ void gbar() {
    __syncthreads();
    if (threadIdx.x == 0) {
        __threadfence();
        unsigned gen = g_bargen;
        if (atomicAdd(&g_barcnt, 1u) == RK_CTAS - 1) {
            g_barcnt = 0;
            __threadfence();
            g_bargen = gen + 1;
        } else {
            while (g_bargen == gen) {}
        }
        __threadfence();
    }
    __syncthreads();
}

// ---------------------------------------------------------------------------
// Phase 1: Z = A @ W[0:512,:] + bias (exact R4 kernel — measured 1.8 ms/launch)
// ---------------------------------------------------------------------------
#define AS_STRIDE 264
#define BS_STRIDE 136

__global__ __launch_bounds__(256) void sgemm_bias(
        const float* __restrict__ A,
        const float* __restrict__ W,
        const float* __restrict__ bias,
        float* __restrict__ Z) {
    __shared__ float As2[16 * AS_STRIDE];
    __shared__ float Bs[16 * BS_STRIDE];

    const int tid = threadIdx.x;
    const int m0 = blockIdx.y * 128;
    const int n0 = blockIdx.x * 128;
    const int tx = tid & 15;
    const int ty = tid >> 4;

    ull acc[8][4];
#pragma unroll
    for (int i = 0; i < 8; i++)
#pragma unroll
        for (int j = 0; j < 4; j++) acc[i][j] = 0ull;

    const int ar = tid >> 2, ac4 = tid & 3;
    const int br = tid >> 5, bc4 = tid & 31;

    for (int k0 = 0; k0 < 512; k0 += 16) {
#pragma unroll
        for (int p = 0; p < 2; p++) {
            int r = ar + p * 64;
            float4 v = *(const float4*)(A + (size_t)(m0 + r) * 512 + k0 + ac4 * 4);
            const float* vf = (const float*)&v;
#pragma unroll
            for (int q = 0; q < 4; q++) {
                As2[(ac4 * 4 + q) * AS_STRIDE + 2 * r]     = vf[q];
                As2[(ac4 * 4 + q) * AS_STRIDE + 2 * r + 1] = vf[q];
            }
        }
#pragma unroll
        for (int p = 0; p < 2; p++) {
            int rB = br + p * 8;
            *(float4*)&Bs[rB * BS_STRIDE + bc4 * 4] =
                *(const float4*)(W + (size_t)(k0 + rB) * ZC_ + n0 + bc4 * 4);
        }
        __syncthreads();

#pragma unroll
        for (int kk = 0; kk < 16; kk++) {
            ull a[8], b[4];
            {
                const ulonglong2* ap = (const ulonglong2*)&As2[kk * AS_STRIDE + 8 * ty];
                ulonglong2 a01 = ap[0], a23 = ap[1];
                a[0] = a01.x; a[1] = a01.y; a[2] = a23.x; a[3] = a23.y;
                const ulonglong2* ap2 = (const ulonglong2*)&As2[kk * AS_STRIDE + 128 + 8 * ty];
                ulonglong2 a45 = ap2[0], a67 = ap2[1];
                a[4] = a45.x; a[5] = a45.y; a[6] = a67.x; a[7] = a67.y;
            }
            {
                ulonglong2 b01 = *(const ulonglong2*)&Bs[kk * BS_STRIDE + 4 * tx];
                ulonglong2 b23 = *(const ulonglong2*)&Bs[kk * BS_STRIDE + 64 + 4 * tx];
                b[0] = b01.x; b[1] = b01.y; b[2] = b23.x; b[3] = b23.y;
            }
#pragma unroll
            for (int i = 0; i < 8; i++)
#pragma unroll
                for (int j = 0; j < 4; j++)
                    ffma2(acc[i][j], a[i], b[j]);
        }
        __syncthreads();
    }

    float4 bv0 = *(const float4*)(bias + n0 + 4 * tx);
    float4 bv1 = *(const float4*)(bias + n0 + 64 + 4 * tx);
#pragma unroll
    for (int i = 0; i < 8; i++) {
        int m = m0 + ((i < 4) ? (ty * 4 + i) : (64 + ty * 4 + (i - 4)));
        float x0, x1, x2, x3;
        unpack2(acc[i][0], x0, x1);
        unpack2(acc[i][1], x2, x3);
        float4 o0 = make_float4(x0 + bv0.x, x1 + bv0.y, x2 + bv0.z, x3 + bv0.w);
        *(float4*)(Z + (size_t)m * ZC_ + n0 + 4 * tx) = o0;
        unpack2(acc[i][2], x0, x1);
        unpack2(acc[i][3], x2, x3);
        float4 o1 = make_float4(x0 + bv1.x, x1 + bv1.y, x2 + bv1.z, x3 + bv1.w);
        *(float4*)(Z + (size_t)m * ZC_ + n0 + 64 + 4 * tx) = o1;
    }
}

// ---------------------------------------------------------------------------
// Phase 2: persistent recurrence, 512 threads (4 warps/SMSP for latency hiding).
// CTA owns 4 h-columns. Warp wid owns k-range [wid*32, wid*32+32).
// Lane: kk_sub = lane>>4 (2 k-rows/warp-iter), b4 = (lane&15)*4 (4 batch rows).
// Per k per thread: 1 LDG.128 (h, coalesced), 4 packs, 4 LDS.128 (w, broadcast),
// 32 FFMA2  ->  9 overhead / 32 FFMA2 (was 6/8).
// Partials per k-group (32 groups) in 128 KB smem; 256 finalizers reduce with
// packed FADD2, gate, update state. Central atomic barrier per step.
// Dynamic smem: W 32 KB + partials 128 KB = 160 KB (<= 227 KB).
// ---------------------------------------------------------------------------
__global__ __launch_bounds__(RK_THR, 1) void lstm_rec(
        const float* __restrict__ Wh,     // [512, 2048] recurrent rows of W
        const float* __restrict__ h0l,    // [512]
        const float* __restrict__ c0l,    // [512]
        float* __restrict__ hseq,         // [T*BS*HC], layout [m][512]
        float* __restrict__ hs_out,       // [BS*HC]
        float* __restrict__ cs_out) {     // [BS*HC]
    extern __shared__ float smem[];
    float* Wsm = smem;                    // [512][16] floats = 32 KB
    ull*   Rsm = (ull*)(smem + 8192);     // [32 kg][4 c][2 p][64 b] ull = 128 KB

    const int tid  = threadIdx.x;
    const int cid  = blockIdx.x;
    const int j0   = cid << 2;
    const int wid  = tid >> 5, lane = tid & 31;
    const int kk_sub = lane >> 4;         // 0..1
    const int b4     = (lane & 15) << 2;  // 0,4,...,60
    const int kbase  = wid << 5;          // 32 k per warp
    const int kg     = (wid << 1) + kk_sub;

    // Weights: Wsm[k*16 + c*4 + g] = Wh[k][g*512 + j0 + c]; ull pairs (f,i),(o,g)
    for (int idx = tid; idx < HC_ * 16; idx += RK_THR) {
        int k = idx >> 4, c = (idx >> 2) & 3, g = idx & 3;
        Wsm[idx] = Wh[(size_t)k * ZC_ + (size_t)g * HC_ + j0 + c];
    }

    // Finalizer identity (tid < 256): (col fc, batch fb)
    const int fc = tid >> 6;
    const int fb = tid & 63;
    const int fj = j0 + fc;
    float cstate = 0.f, hlast = 0.f;
    if (tid < 256) {
        cstate = c0l[fj];
        hlast  = h0l[fj];
        __stcg(&g_hbuf[0][fj * BSZ + fb], hlast);
    }
    gbar();

    for (int t = 0; t < TT; t++) {
        // z prefetch (finalizers only; consumed after reduction)
        float z0 = 0.f, z1 = 0.f, z2 = 0.f, z3 = 0.f;
        if (tid < 256) {
            const float* zr = g_z + (size_t)(t * BSZ + fb) * ZC_ + fj;
            z0 = __ldcg(zr);
            z1 = __ldcg(zr + HC_);
            z2 = __ldcg(zr + 2 * HC_);
            z3 = __ldcg(zr + 3 * HC_);
        }

        const float* hb = g_hbuf[t & 1] + b4;
        ull acc[4][4][2];                 // [b][c][p]
#pragma unroll
        for (int b = 0; b < 4; b++)
#pragma unroll
            for (int c = 0; c < 4; c++) { acc[b][c][0] = 0ull; acc[b][c][1] = 0ull; }

        // Depth-2 software pipeline on the h loads (L2 latency ~240 cyc)
        float4 h0 = __ldcg((const float4*)(hb + (kbase + kk_sub) * BSZ));
        float4 h1 = __ldcg((const float4*)(hb + (kbase + 2 + kk_sub) * BSZ));

#pragma unroll
        for (int i = 0; i < 16; i++) {
            float4 cur = h0;
            h0 = h1;
            if (i < 14)
                h1 = __ldcg((const float4*)(hb + (kbase + (i + 2) * 2 + kk_sub) * BSZ));

            const int k = kbase + i * 2 + kk_sub;
            const float* wrow = Wsm + k * 16;
            ull w[4][2];
#pragma unroll
            for (int c = 0; c < 4; c++) {
                ulonglong2 w2 = *(const ulonglong2*)(wrow + c * 4);
                w[c][0] = w2.x; w[c][1] = w2.y;
            }
            ull hp[4];
            hp[0] = pack2(cur.x, cur.x);
            hp[1] = pack2(cur.y, cur.y);
            hp[2] = pack2(cur.z, cur.z);
            hp[3] = pack2(cur.w, cur.w);
#pragma unroll
            for (int b = 0; b < 4; b++)
#pragma unroll
                for (int c = 0; c < 4; c++) {
                    ffma2(acc[b][c][0], hp[b], w[c][0]);
                    ffma2(acc[b][c][1], hp[b], w[c][1]);
                }
        }

        // Store partials: Rsm[((kg*4 + c)*2 + p)*64 + b], b-pairs via 16B stores
#pragma unroll
        for (int c = 0; c < 4; c++)
#pragma unroll
            for (int p = 0; p < 2; p++) {
                ull* dst = Rsm + ((size_t)(kg * 4 + c) * 2 + p) * 64 + b4;
                *(ulonglong2*)(dst)     = make_ulonglong2(acc[0][c][p], acc[1][c][p]);
                *(ulonglong2*)(dst + 2) = make_ulonglong2(acc[2][c][p], acc[3][c][p]);
            }
        __syncthreads();

        // Finalize: sum 32 k-group partials (packed adds), gate, update state
        if (tid < 256) {
            ull s0 = 0ull, s1 = 0ull;
#pragma unroll
            for (int q = 0; q < 32; q++) {
                fadd2(s0, Rsm[((size_t)(q * 4 + fc) * 2 + 0) * 64 + fb]);
                fadd2(s1, Rsm[((size_t)(q * 4 + fc) * 2 + 1) * 64 + fb]);
            }
            float f, i, o, g;
            unpack2(s0, f, i);
            unpack2(s1, o, g);
            f += z0; i += z1; o += z2; g += z3;
            f = sigf(f + 1.0f);           // FORGET_BIAS
            i = sigf(i);
            o = sigf(o);
            g = tanh_fast(g);
            cstate = cstate * f + g * i;
            hlast = o * tanh_fast(cstate);

            __stcg(&g_hbuf[(t + 1) & 1][fj * BSZ + fb], hlast);
            hseq[(size_t)(t * BSZ + fb) * HC_ + fj] = hlast;
        }
        gbar();
    }

    if (tid < 256) {
        hs_out[fb * HC_ + fj] = hlast;
        cs_out[fb * HC_ + fj] = cstate;
    }
}

#define RK_SMEM (160 * 1024)

// ---------------------------------------------------------------------------
// Launch: sgemm(L0) -> rec(L0) -> sgemm(L1) -> rec(L1 -> d_out)
// ---------------------------------------------------------------------------
extern "C" void kernel_launch(void* const* d_in, const int* in_sizes, int n_in,
                              void* d_out, int out_size) {
    const float* x  = (const float*)d_in[0];
    const float* W0 = (const float*)d_in[1];
    const float* b0 = (const float*)d_in[2];
    const float* W1 = (const float*)d_in[3];
    const float* b1 = (const float*)d_in[4];
    const float* h0 = (const float*)d_in[5];
    const float* c0 = (const float*)d_in[6];

    float* out = (float*)d_out;                      // [T, BS, HC]
    float* hs  = out + (size_t)TT * BSZ * HC_;       // [L, BS, HC]
    float* cs  = hs + (size_t)2 * BSZ * HC_;         // [L, BS, HC]

    float* zptr = nullptr;
    float* hseq0 = nullptr;
    cudaGetSymbolAddress((void**)&zptr, g_z);
    cudaGetSymbolAddress((void**)&hseq0, g_hseq);

    static int smem_set = 0;
    if (!smem_set) {
        cudaFuncSetAttribute(lstm_rec, cudaFuncAttributeMaxDynamicSharedMemorySize, RK_SMEM);
        smem_set = 1;
    }

    dim3 ggrid(ZC_ / 128, MR / 128);

    // Layer 0
    sgemm_bias<<<ggrid, 256>>>(x, W0, b0, zptr);
    lstm_rec<<<RK_CTAS, RK_THR, RK_SMEM>>>(W0 + (size_t)IC_ * ZC_, h0, c0,
                                           hseq0, hs, cs);
    // Layer 1
    sgemm_bias<<<ggrid, 256>>>(hseq0, W1, b1, zptr);
    lstm_rec<<<RK_CTAS, RK_THR, RK_SMEM>>>(W1 + (size_t)HC_ * ZC_, h0 + HC_, c0 + HC_,
                                           out, hs + BSZ * HC_, cs + BSZ * HC_);
}

// round 8
// speedup vs baseline: 1.7001x; 1.1612x over previous
#include <cuda_runtime.h>
#include <cstdint>
#include <cstddef>

// Problem constants
#define TT   512
#define BSZ  64
#define IC_  512
#define HC_  512
#define ZC_  2048
#define MR   (TT*BSZ)

#define RK_CTAS 128
#define RK_THR  512
#define NGRP    4          // batch groups (16 rows each)
#define GCTAS   32         // col-block CTAs per group

typedef unsigned long long ull;

// ---------------------------------------------------------------------------
// Static device scratch (no cudaMalloc allowed)
// ---------------------------------------------------------------------------
__device__ float g_z[(size_t)MR * ZC_];        // 256 MB: x-projection (+bias), [m][2048]
__device__ float g_hseq[(size_t)MR * HC_];     // 64 MB: layer-0 h sequence [m][512]
__device__ float g_hg[2][NGRP][HC_][16];       // double-buffered h per group: [k][b16]
__device__ unsigned g_bcnt[NGRP * 32];         // per-group barrier counters (padded 128B)
__device__ volatile unsigned g_bgen[NGRP * 32];

// ---------------------------------------------------------------------------
// f32x2 helpers (Blackwell packed fp32 — SASS FFMA2 / FADD2)
// ---------------------------------------------------------------------------
__device__ __forceinline__ ull pack2(float x, float y) {
    ull r; asm("mov.b64 %0, {%1, %2};" : "=l"(r) : "f"(x), "f"(y)); return r;
}
__device__ __forceinline__ void unpack2(ull v, float& x, float& y) {
    asm("mov.b64 {%0, %1}, %2;" : "=f"(x), "=f"(y) : "l"(v));
}
__device__ __forceinline__ void ffma2(ull& d, ull a, ull b) {
    asm("fma.rn.f32x2 %0, %1, %2, %0;" : "+l"(d) : "l"(a), "l"(b));
}
__device__ __forceinline__ void fadd2(ull& d, ull a) {
    asm("add.rn.f32x2 %0, %0, %1;" : "+l"(d) : "l"(a));
}

__device__ __forceinline__ float sigf(float x) { return 1.0f / (1.0f + __expf(-x)); }
__device__ __forceinline__ float tanh_fast(float x) {
    float ax = fabsf(x);
    float e = __expf(-2.0f * ax);
    float r = (1.0f - e) / (1.0f + e);
    return copysignf(r, x);
}

// Group-local barrier: only the 32 CTAs of one batch-group synchronize.
__device__ __forceinline__ void gbar_grp(int grp) {
    __syncthreads();
    if (threadIdx.x == 0) {
        __threadfence();
        unsigned gen = g_bgen[grp * 32];
        if (atomicAdd(&g_bcnt[grp * 32], 1u) == GCTAS - 1) {
            g_bcnt[grp * 32] = 0;
            __threadfence();
            g_bgen[grp * 32] = gen + 1;
        } else {
            while (g_bgen[grp * 32] == gen) {}
        }
        __threadfence();
    }
    __syncthreads();
}

// ---------------------------------------------------------------------------
// Phase 1: Z = A @ W[0:512,:] + bias (R4-exact SGEMM, ~1.8 ms/launch measured)
// ---------------------------------------------------------------------------
#define AS_STRIDE 264
#define BS_STRIDE 136

__global__ __launch_bounds__(256) void sgemm_bias(
        const float* __restrict__ A,
        const float* __restrict__ W,
        const float* __restrict__ bias,
        float* __restrict__ Z) {
    __shared__ float As2[16 * AS_STRIDE];
    __shared__ float Bs[16 * BS_STRIDE];

    const int tid = threadIdx.x;
    const int m0 = blockIdx.y * 128;
    const int n0 = blockIdx.x * 128;
    const int tx = tid & 15;
    const int ty = tid >> 4;

    ull acc[8][4];
#pragma unroll
    for (int i = 0; i < 8; i++)
#pragma unroll
        for (int j = 0; j < 4; j++) acc[i][j] = 0ull;

    const int ar = tid >> 2, ac4 = tid & 3;
    const int br = tid >> 5, bc4 = tid & 31;

    for (int k0 = 0; k0 < 512; k0 += 16) {
#pragma unroll
        for (int p = 0; p < 2; p++) {
            int r = ar + p * 64;
            float4 v = *(const float4*)(A + (size_t)(m0 + r) * 512 + k0 + ac4 * 4);
            const float* vf = (const float*)&v;
#pragma unroll
            for (int q = 0; q < 4; q++) {
                As2[(ac4 * 4 + q) * AS_STRIDE + 2 * r]     = vf[q];
                As2[(ac4 * 4 + q) * AS_STRIDE + 2 * r + 1] = vf[q];
            }
        }
#pragma unroll
        for (int p = 0; p < 2; p++) {
            int rB = br + p * 8;
            *(float4*)&Bs[rB * BS_STRIDE + bc4 * 4] =
                *(const float4*)(W + (size_t)(k0 + rB) * ZC_ + n0 + bc4 * 4);
        }
        __syncthreads();

#pragma unroll
        for (int kk = 0; kk < 16; kk++) {
            ull a[8], b[4];
            {
                const ulonglong2* ap = (const ulonglong2*)&As2[kk * AS_STRIDE + 8 * ty];
                ulonglong2 a01 = ap[0], a23 = ap[1];
                a[0] = a01.x; a[1] = a01.y; a[2] = a23.x; a[3] = a23.y;
                const ulonglong2* ap2 = (const ulonglong2*)&As2[kk * AS_STRIDE + 128 + 8 * ty];
                ulonglong2 a45 = ap2[0], a67 = ap2[1];
                a[4] = a45.x; a[5] = a45.y; a[6] = a67.x; a[7] = a67.y;
            }
            {
                ulonglong2 b01 = *(const ulonglong2*)&Bs[kk * BS_STRIDE + 4 * tx];
                ulonglong2 b23 = *(const ulonglong2*)&Bs[kk * BS_STRIDE + 64 + 4 * tx];
                b[0] = b01.x; b[1] = b01.y; b[2] = b23.x; b[3] = b23.y;
            }
#pragma unroll
            for (int i = 0; i < 8; i++)
#pragma unroll
                for (int j = 0; j < 4; j++)
                    ffma2(acc[i][j], a[i], b[j]);
        }
        __syncthreads();
    }

    float4 bv0 = *(const float4*)(bias + n0 + 4 * tx);
    float4 bv1 = *(const float4*)(bias + n0 + 64 + 4 * tx);
#pragma unroll
    for (int i = 0; i < 8; i++) {
        int m = m0 + ((i < 4) ? (ty * 4 + i) : (64 + ty * 4 + (i - 4)));
        float x0, x1, x2, x3;
        unpack2(acc[i][0], x0, x1);
        unpack2(acc[i][1], x2, x3);
        float4 o0 = make_float4(x0 + bv0.x, x1 + bv0.y, x2 + bv0.z, x3 + bv0.w);
        *(float4*)(Z + (size_t)m * ZC_ + n0 + 4 * tx) = o0;
        unpack2(acc[i][2], x0, x1);
        unpack2(acc[i][3], x2, x3);
        float4 o1 = make_float4(x0 + bv1.x, x1 + bv1.y, x2 + bv1.z, x3 + bv1.w);
        *(float4*)(Z + (size_t)m * ZC_ + n0 + 64 + 4 * tx) = o1;
    }
}

// ---------------------------------------------------------------------------
// Phase 2: persistent recurrence, group-decomposed sync.
// 128 CTAs = 4 batch-groups x 32 col-blocks. CTA: 16 batch x 16 h-cols,
// full k=512. Only the 32 CTAs of a group synchronize (group barrier);
// the 4 groups run fully decoupled for all 512 steps.
// 512 threads: warp wid owns k in [wid*32, wid*32+32). Lane: ch = lane>>2
// (8 gate-col octets), b4 = (lane&3)*4 (float4 of the 16 group-batch rows).
// Per k: 1 LDG.128 (h), 2 LDS.128 (w), 4 packs, 16 FFMA2.
// Partials: [16 kg][34 cp(pad 17)][16 b] ull in smem; 256 finalizers reduce.
// Smem: W 128 KB + partials 68 KB = 196 KB.
// ---------------------------------------------------------------------------
#define CPSTRIDE 17      // padded ull stride per col-pair row

__global__ __launch_bounds__(RK_THR, 1) void lstm_rec(
        const float* __restrict__ Wh,     // [512, 2048] recurrent rows of W
        const float* __restrict__ h0l,    // [512]
        const float* __restrict__ c0l,    // [512]
        float* __restrict__ hseq,         // [T*BS*HC], layout [m][512]
        float* __restrict__ hs_out,       // [BS*HC]
        float* __restrict__ cs_out) {     // [BS*HC]
    extern __shared__ float smem[];
    float* Wsm = smem;                        // [512][64] = 128 KB, c = hcol*4+gate
    ull*   Rsm = (ull*)(smem + 512 * 64);     // [16 kg][32 cp pad 17][16 b] = 69.6KB

    const int tid  = threadIdx.x;
    const int cid  = blockIdx.x;
    const int grp  = cid & 3;             // batch group
    const int cb   = cid >> 2;            // col block (0..31)
    const int wid  = tid >> 5, lane = tid & 31;
    const int ch   = lane >> 2;           // 0..7: gate-col octet
    const int b4   = (lane & 3) << 2;     // 0,4,8,12
    const int kbase = wid << 5;

    // Weights: Wsm[k*64 + hcol*4 + gate] = Wh[k][gate*512 + cb*16 + hcol]
    for (int idx = tid; idx < 512 * 64; idx += RK_THR) {
        int k = idx >> 6, c = idx & 63;
        int hcol = c >> 2, gate = c & 3;
        Wsm[idx] = Wh[(size_t)k * ZC_ + (size_t)gate * HC_ + cb * 16 + hcol];
    }

    // Finalizer identity (tid < 256): fcol fast for coalesced z/hseq access
    const int fcol = tid & 15;            // h-col within block
    const int fb   = tid >> 4;            // batch row within group
    const int hcg  = cb * 16 + fcol;      // global h-col
    const int B    = grp * 16 + fb;       // global batch row
    float cstate = 0.f, hlast = 0.f;
    if (tid < 256) {
        cstate = c0l[hcg];
        hlast  = h0l[hcg];
        __stcg(&g_hg[0][grp][hcg][fb], hlast);
    }
    gbar_grp(grp);

    for (int t = 0; t < TT; t++) {
        // z prefetch (finalizers; 64B-coalesced since fcol is fast index)
        float z0 = 0.f, z1 = 0.f, z2 = 0.f, z3 = 0.f;
        if (tid < 256) {
            const float* zr = g_z + (size_t)(t * BSZ + B) * ZC_ + hcg;
            z0 = __ldcg(zr);
            z1 = __ldcg(zr + HC_);
            z2 = __ldcg(zr + 2 * HC_);
            z3 = __ldcg(zr + 3 * HC_);
        }

        const float* hb = &g_hg[t & 1][grp][0][0] + b4;
        ull acc[4][4];                    // [b][q: col-pair within octet]
#pragma unroll
        for (int b = 0; b < 4; b++)
#pragma unroll
            for (int q = 0; q < 4; q++) acc[b][q] = 0ull;

        // Depth-3 pipelined h loads from the group's 32 KB L2-resident buffer
        float4 hA = __ldcg((const float4*)(hb + (kbase + 0) * 16));
        float4 hB = __ldcg((const float4*)(hb + (kbase + 1) * 16));
        float4 hC = __ldcg((const float4*)(hb + (kbase + 2) * 16));

#pragma unroll
        for (int i = 0; i < 32; i++) {
            float4 cur = hA;
            hA = hB; hB = hC;
            if (i < 29)
                hC = __ldcg((const float4*)(hb + (kbase + i + 3) * 16));

            const int k = kbase + i;
            const ulonglong2* wp = (const ulonglong2*)(Wsm + k * 64 + ch * 8);
            ulonglong2 w01 = wp[0], w23 = wp[1];
            ull hp[4];
            hp[0] = pack2(cur.x, cur.x);
            hp[1] = pack2(cur.y, cur.y);
            hp[2] = pack2(cur.z, cur.z);
            hp[3] = pack2(cur.w, cur.w);
#pragma unroll
            for (int b = 0; b < 4; b++) {
                ffma2(acc[b][0], hp[b], w01.x);
                ffma2(acc[b][1], hp[b], w01.y);
                ffma2(acc[b][2], hp[b], w23.x);
                ffma2(acc[b][3], hp[b], w23.y);
            }
        }

        // Partials: Rsm[kg*544 + cp*17 + b]
        {
            ull* base = Rsm + (size_t)wid * (32 * CPSTRIDE);
#pragma unroll
            for (int q = 0; q < 4; q++) {
                ull* row = base + (ch * 4 + q) * CPSTRIDE + b4;
                row[0] = acc[0][q];
                row[1] = acc[1][q];
                row[2] = acc[2][q];
                row[3] = acc[3][q];
            }
        }
        __syncthreads();

        // Finalize: sum 16 k-group partials, gate, update state
        if (tid < 256) {
            ull s0 = 0ull, s1 = 0ull;
            const ull* r0 = Rsm + (fcol * 2 + 0) * CPSTRIDE + fb;
            const ull* r1 = Rsm + (fcol * 2 + 1) * CPSTRIDE + fb;
#pragma unroll
            for (int kg = 0; kg < 16; kg++) {
                fadd2(s0, r0[kg * 32 * CPSTRIDE]);
                fadd2(s1, r1[kg * 32 * CPSTRIDE]);
            }
            float f, i, o, g;
            unpack2(s0, f, i);
            unpack2(s1, o, g);
            f += z0; i += z1; o += z2; g += z3;
            f = sigf(f + 1.0f);           // FORGET_BIAS
            i = sigf(i);
            o = sigf(o);
            g = tanh_fast(g);
            cstate = cstate * f + g * i;
            hlast = o * tanh_fast(cstate);

            __stcg(&g_hg[(t + 1) & 1][grp][hcg][fb], hlast);
            hseq[(size_t)(t * BSZ + B) * HC_ + hcg] = hlast;
        }
        gbar_grp(grp);
    }

    if (tid < 256) {
        hs_out[B * HC_ + hcg] = hlast;
        cs_out[B * HC_ + hcg] = cstate;
    }
}

#define RK_SMEM (512 * 64 * 4 + 16 * 32 * CPSTRIDE * 8)   // 131072 + 69632 = 200704

// ---------------------------------------------------------------------------
// Launch: sgemm(L0) -> rec(L0) -> sgemm(L1) -> rec(L1 -> d_out)
// ---------------------------------------------------------------------------
extern "C" void kernel_launch(void* const* d_in, const int* in_sizes, int n_in,
                              void* d_out, int out_size) {
    const float* x  = (const float*)d_in[0];
    const float* W0 = (const float*)d_in[1];
    const float* b0 = (const float*)d_in[2];
    const float* W1 = (const float*)d_in[3];
    const float* b1 = (const float*)d_in[4];
    const float* h0 = (const float*)d_in[5];
    const float* c0 = (const float*)d_in[6];

    float* out = (float*)d_out;                      // [T, BS, HC]
    float* hs  = out + (size_t)TT * BSZ * HC_;       // [L, BS, HC]
    float* cs  = hs + (size_t)2 * BSZ * HC_;         // [L, BS, HC]

    float* zptr = nullptr;
    float* hseq0 = nullptr;
    cudaGetSymbolAddress((void**)&zptr, g_z);
    cudaGetSymbolAddress((void**)&hseq0, g_hseq);

    static int smem_set = 0;
    if (!smem_set) {
        cudaFuncSetAttribute(lstm_rec, cudaFuncAttributeMaxDynamicSharedMemorySize, RK_SMEM);
        smem_set = 1;
    }

    dim3 ggrid(ZC_ / 128, MR / 128);

    // Layer 0
    sgemm_bias<<<ggrid, 256>>>(x, W0, b0, zptr);
    lstm_rec<<<RK_CTAS, RK_THR, RK_SMEM>>>(W0 + (size_t)IC_ * ZC_, h0, c0,
                                           hseq0, hs, cs);
    // Layer 1
    sgemm_bias<<<ggrid, 256>>>(hseq0, W1, b1, zptr);
    lstm_rec<<<RK_CTAS, RK_THR, RK_SMEM>>>(W1 + (size_t)HC_ * ZC_, h0 + HC_, c0 + HC_,
                                           out, hs + BSZ * HC_, cs + BSZ * HC_);
}

// round 9
// speedup vs baseline: 1.8812x; 1.1065x over previous
#include <cuda_runtime.h>
#include <cstdint>
#include <cstddef>

// Problem constants
#define TT   512
#define BSZ  64
#define IC_  512
#define HC_  512
#define ZC_  2048
#define MR   (TT*BSZ)

#define RK_CTAS 128
#define RK_THR  512
#define NGRP    4          // batch groups (16 rows each)
#define GCTAS   32         // col-block CTAs per group

typedef unsigned long long ull;

// ---------------------------------------------------------------------------
// Static device scratch (no cudaMalloc allowed)
// ---------------------------------------------------------------------------
__device__ float g_z[(size_t)MR * ZC_];        // 256 MB: x-projection (+bias), [m][2048]
__device__ float g_hseq[(size_t)MR * HC_];     // 64 MB: layer-0 h sequence [m][512]
__device__ float g_hg[2][NGRP][HC_][16];       // double-buffered h per group: [k][b16]
__device__ unsigned g_bcnt[NGRP * 32];         // per-group barrier counters (128B apart)
__device__ unsigned g_bgen[NGRP * 32];         // per-group generation

// ---------------------------------------------------------------------------
// f32x2 helpers (Blackwell packed fp32 — SASS FFMA2 / FADD2)
// ---------------------------------------------------------------------------
__device__ __forceinline__ ull pack2(float x, float y) {
    ull r; asm("mov.b64 %0, {%1, %2};" : "=l"(r) : "f"(x), "f"(y)); return r;
}
__device__ __forceinline__ void unpack2(ull v, float& x, float& y) {
    asm("mov.b64 {%0, %1}, %2;" : "=f"(x), "=f"(y) : "l"(v));
}
__device__ __forceinline__ void ffma2(ull& d, ull a, ull b) {
    asm("fma.rn.f32x2 %0, %1, %2, %0;" : "+l"(d) : "l"(a), "l"(b));
}
__device__ __forceinline__ void fadd2(ull& d, ull a) {
    asm("add.rn.f32x2 %0, %0, %1;" : "+l"(d) : "l"(a));
}

// acquire/release sync primitives (gpu scope) — no full membar drains
__device__ __forceinline__ unsigned atom_add_acqrel(unsigned* p, unsigned v) {
    unsigned old;
    asm volatile("atom.global.add.acq_rel.gpu.u32 %0, [%1], %2;"
                 : "=r"(old) : "l"(p), "r"(v) : "memory");
    return old;
}
__device__ __forceinline__ unsigned ld_acquire(const unsigned* p) {
    unsigned v;
    asm volatile("ld.global.acquire.gpu.u32 %0, [%1];" : "=r"(v) : "l"(p) : "memory");
    return v;
}
__device__ __forceinline__ void st_release(unsigned* p, unsigned v) {
    asm volatile("st.global.release.gpu.u32 [%0], %1;" :: "l"(p), "r"(v) : "memory");
}

__device__ __forceinline__ float sigf(float x) { return 1.0f / (1.0f + __expf(-x)); }
__device__ __forceinline__ float tanh_fast(float x) {
    float ax = fabsf(x);
    float e = __expf(-2.0f * ax);
    float r = (1.0f - e) / (1.0f + e);
    return copysignf(r, x);
}

// ---------------------------------------------------------------------------
// Phase 1: Z = A @ W[0:512,:] + bias via FFMA2.
// Double-buffered smem (one sync per BK-tile, loads overlapped with compute),
// 2 CTAs/SM enforced. Tile M=128,N=128,BK=16, per-thread 8x8 (32 FFMA2).
// ---------------------------------------------------------------------------
#define AS_STRIDE 264
#define BS_STRIDE 136

__global__ __launch_bounds__(256, 2) void sgemm_bias(
        const float* __restrict__ A,
        const float* __restrict__ W,
        const float* __restrict__ bias,
        float* __restrict__ Z) {
    __shared__ float As2[2][16 * AS_STRIDE];   // dup'd A: 2 x 16.5 KB
    __shared__ float Bs[2][16 * BS_STRIDE];    // 2 x 8.5 KB

    const int tid = threadIdx.x;
    const int m0 = blockIdx.y * 128;
    const int n0 = blockIdx.x * 128;
    const int tx = tid & 15;
    const int ty = tid >> 4;

    ull acc[8][4];
#pragma unroll
    for (int i = 0; i < 8; i++)
#pragma unroll
        for (int j = 0; j < 4; j++) acc[i][j] = 0ull;

    const int ar = tid >> 2, ac4 = tid & 3;
    const int br = tid >> 5, bc4 = tid & 31;

    // Prologue: stage tile 0 into buffer 0
    {
#pragma unroll
        for (int p = 0; p < 2; p++) {
            int r = ar + p * 64;
            float4 v = *(const float4*)(A + (size_t)(m0 + r) * 512 + ac4 * 4);
            const float* vf = (const float*)&v;
#pragma unroll
            for (int q = 0; q < 4; q++) {
                As2[0][(ac4 * 4 + q) * AS_STRIDE + 2 * r]     = vf[q];
                As2[0][(ac4 * 4 + q) * AS_STRIDE + 2 * r + 1] = vf[q];
            }
        }
#pragma unroll
        for (int p = 0; p < 2; p++) {
            int rB = br + p * 8;
            *(float4*)&Bs[0][rB * BS_STRIDE + bc4 * 4] =
                *(const float4*)(W + (size_t)rB * ZC_ + n0 + bc4 * 4);
        }
    }
    __syncthreads();

    for (int it = 0; it < 32; it++) {
        const int cur = it & 1;
        float4 aPf[2], bPf[2];
        if (it < 31) {
            const int k0n = (it + 1) * 16;
#pragma unroll
            for (int p = 0; p < 2; p++)
                aPf[p] = *(const float4*)(A + (size_t)(m0 + ar + p * 64) * 512 + k0n + ac4 * 4);
#pragma unroll
            for (int p = 0; p < 2; p++)
                bPf[p] = *(const float4*)(W + (size_t)(k0n + br + p * 8) * ZC_ + n0 + bc4 * 4);
        }

#pragma unroll
        for (int kk = 0; kk < 16; kk++) {
            ull a[8], b[4];
            {
                const ulonglong2* ap = (const ulonglong2*)&As2[cur][kk * AS_STRIDE + 8 * ty];
                ulonglong2 a01 = ap[0], a23 = ap[1];
                a[0] = a01.x; a[1] = a01.y; a[2] = a23.x; a[3] = a23.y;
                const ulonglong2* ap2 = (const ulonglong2*)&As2[cur][kk * AS_STRIDE + 128 + 8 * ty];
                ulonglong2 a45 = ap2[0], a67 = ap2[1];
                a[4] = a45.x; a[5] = a45.y; a[6] = a67.x; a[7] = a67.y;
            }
            {
                ulonglong2 b01 = *(const ulonglong2*)&Bs[cur][kk * BS_STRIDE + 4 * tx];
                ulonglong2 b23 = *(const ulonglong2*)&Bs[cur][kk * BS_STRIDE + 64 + 4 * tx];
                b[0] = b01.x; b[1] = b01.y; b[2] = b23.x; b[3] = b23.y;
            }
#pragma unroll
            for (int i = 0; i < 8; i++)
#pragma unroll
                for (int j = 0; j < 4; j++)
                    ffma2(acc[i][j], a[i], b[j]);
        }

        if (it < 31) {
            const int nxt = cur ^ 1;
#pragma unroll
            for (int p = 0; p < 2; p++) {
                int r = ar + p * 64;
                const float* vf = (const float*)&aPf[p];
#pragma unroll
                for (int q = 0; q < 4; q++) {
                    As2[nxt][(ac4 * 4 + q) * AS_STRIDE + 2 * r]     = vf[q];
                    As2[nxt][(ac4 * 4 + q) * AS_STRIDE + 2 * r + 1] = vf[q];
                }
            }
#pragma unroll
            for (int p = 0; p < 2; p++)
                *(float4*)&Bs[nxt][(br + p * 8) * BS_STRIDE + bc4 * 4] = bPf[p];
        }
        __syncthreads();
    }

    float4 bv0 = *(const float4*)(bias + n0 + 4 * tx);
    float4 bv1 = *(const float4*)(bias + n0 + 64 + 4 * tx);
#pragma unroll
    for (int i = 0; i < 8; i++) {
        int m = m0 + ((i < 4) ? (ty * 4 + i) : (64 + ty * 4 + (i - 4)));
        float x0, x1, x2, x3;
        unpack2(acc[i][0], x0, x1);
        unpack2(acc[i][1], x2, x3);
        float4 o0 = make_float4(x0 + bv0.x, x1 + bv0.y, x2 + bv0.z, x3 + bv0.w);
        *(float4*)(Z + (size_t)m * ZC_ + n0 + 4 * tx) = o0;
        unpack2(acc[i][2], x0, x1);
        unpack2(acc[i][3], x2, x3);
        float4 o1 = make_float4(x0 + bv1.x, x1 + bv1.y, x2 + bv1.z, x3 + bv1.w);
        *(float4*)(Z + (size_t)m * ZC_ + n0 + 64 + 4 * tx) = o1;
    }
}

// ---------------------------------------------------------------------------
// Phase 2: persistent recurrence, group-decomposed acq/rel sync.
// 128 CTAs = 4 batch-groups x 32 col-blocks. CTA: 16 batch x 16 h-cols, k=512.
// Barrier: arrive via atom.add.acq_rel; leader resets + st.release gen;
// pollers ld.acquire. hseq store issued between arrive and poll (drains
// during the wait; not ordered by the release — consumed only next kernel).
// ---------------------------------------------------------------------------
#define CPSTRIDE 17      // padded ull stride per col-pair row

__global__ __launch_bounds__(RK_THR, 1) void lstm_rec(
        const float* __restrict__ Wh,     // [512, 2048] recurrent rows of W
        const float* __restrict__ h0l,    // [512]
        const float* __restrict__ c0l,    // [512]
        float* __restrict__ hseq,         // [T*BS*HC], layout [m][512]
        float* __restrict__ hs_out,       // [BS*HC]
        float* __restrict__ cs_out) {     // [BS*HC]
    extern __shared__ float smem[];
    float* Wsm = smem;                        // [512][64] = 128 KB, c = hcol*4+gate
    ull*   Rsm = (ull*)(smem + 512 * 64);     // [16 kg][32 cp pad 17][16 b] = 69.6KB

    const int tid  = threadIdx.x;
    const int cid  = blockIdx.x;
    const int grp  = cid & 3;             // batch group
    const int cb   = cid >> 2;            // col block (0..31)
    const int wid  = tid >> 5, lane = tid & 31;
    const int ch   = lane >> 2;           // 0..7: gate-col octet
    const int b4   = (lane & 3) << 2;     // 0,4,8,12
    const int kbase = wid << 5;

    unsigned* bcnt = &g_bcnt[grp * 32];
    unsigned* bgen = &g_bgen[grp * 32];

    // Weights: Wsm[k*64 + hcol*4 + gate] = Wh[k][gate*512 + cb*16 + hcol]
    for (int idx = tid; idx < 512 * 64; idx += RK_THR) {
        int k = idx >> 6, c = idx & 63;
        int hcol = c >> 2, gate = c & 3;
        Wsm[idx] = Wh[(size_t)k * ZC_ + (size_t)gate * HC_ + cb * 16 + hcol];
    }

    // Finalizer identity (tid < 256): fcol fast for coalesced z/hseq access
    const int fcol = tid & 15;            // h-col within block
    const int fb   = tid >> 4;            // batch row within group
    const int hcg  = cb * 16 + fcol;      // global h-col
    const int B    = grp * 16 + fb;       // global batch row
    float cstate = 0.f, hlast = 0.f;
    if (tid < 256) {
        cstate = c0l[hcg];
        hlast  = h0l[hcg];
        __stcg(&g_hg[0][grp][hcg][fb], hlast);
    }
    // initial barrier
    __syncthreads();
    if (tid == 0) {
        unsigned gen = *bgen;
        unsigned old = atom_add_acqrel(bcnt, 1u);
        if (old == GCTAS - 1) {
            *bcnt = 0;
            st_release(bgen, gen + 1);
        } else {
            while (ld_acquire(bgen) == gen) {}
        }
    }
    __syncthreads();

    for (int t = 0; t < TT; t++) {
        // z prefetch (finalizers; 64B-coalesced since fcol is fast index)
        float z0 = 0.f, z1 = 0.f, z2 = 0.f, z3 = 0.f;
        if (tid < 256) {
            const float* zr = g_z + (size_t)(t * BSZ + B) * ZC_ + hcg;
            z0 = __ldcg(zr);
            z1 = __ldcg(zr + HC_);
            z2 = __ldcg(zr + 2 * HC_);
            z3 = __ldcg(zr + 3 * HC_);
        }

        const float* hb = &g_hg[t & 1][grp][0][0] + b4;
        ull acc[4][4];                    // [b][q: col-pair within octet]
#pragma unroll
        for (int b = 0; b < 4; b++)
#pragma unroll
            for (int q = 0; q < 4; q++) acc[b][q] = 0ull;

        // Depth-3 pipelined h loads (group h buffer is 32 KB, L2-resident)
        float4 hA = __ldcg((const float4*)(hb + (kbase + 0) * 16));
        float4 hB = __ldcg((const float4*)(hb + (kbase + 1) * 16));
        float4 hC = __ldcg((const float4*)(hb + (kbase + 2) * 16));

#pragma unroll
        for (int i = 0; i < 32; i++) {
            float4 cur = hA;
            hA = hB; hB = hC;
            if (i < 29)
                hC = __ldcg((const float4*)(hb + (kbase + i + 3) * 16));

            const int k = kbase + i;
            const ulonglong2* wp = (const ulonglong2*)(Wsm + k * 64 + ch * 8);
            ulonglong2 w01 = wp[0], w23 = wp[1];
            ull hp[4];
            hp[0] = pack2(cur.x, cur.x);
            hp[1] = pack2(cur.y, cur.y);
            hp[2] = pack2(cur.z, cur.z);
            hp[3] = pack2(cur.w, cur.w);
#pragma unroll
            for (int b = 0; b < 4; b++) {
                ffma2(acc[b][0], hp[b], w01.x);
                ffma2(acc[b][1], hp[b], w01.y);
                ffma2(acc[b][2], hp[b], w23.x);
                ffma2(acc[b][3], hp[b], w23.y);
            }
        }

        // Partials: Rsm[kg*544 + cp*17 + b]
        {
            ull* base = Rsm + (size_t)wid * (32 * CPSTRIDE);
#pragma unroll
            for (int q = 0; q < 4; q++) {
                ull* row = base + (ch * 4 + q) * CPSTRIDE + b4;
                row[0] = acc[0][q];
                row[1] = acc[1][q];
                row[2] = acc[2][q];
                row[3] = acc[3][q];
            }
        }
        __syncthreads();

        // Finalize: sum 16 k-group partials, gate, update state
        if (tid < 256) {
            ull s0 = 0ull, s1 = 0ull;
            const ull* r0 = Rsm + (fcol * 2 + 0) * CPSTRIDE + fb;
            const ull* r1 = Rsm + (fcol * 2 + 1) * CPSTRIDE + fb;
#pragma unroll
            for (int kg = 0; kg < 16; kg++) {
                fadd2(s0, r0[kg * 32 * CPSTRIDE]);
                fadd2(s1, r1[kg * 32 * CPSTRIDE]);
            }
            float f, i, o, g;
            unpack2(s0, f, i);
            unpack2(s1, o, g);
            f += z0; i += z1; o += z2; g += z3;
            f = sigf(f + 1.0f);           // FORGET_BIAS
            i = sigf(i);
            o = sigf(o);
            g = tanh_fast(g);
            cstate = cstate * f + g * i;
            hlast = o * tanh_fast(cstate);

            __stcg(&g_hg[(t + 1) & 1][grp][hcg][fb], hlast);
        }

        // Barrier with hseq store folded into the wait window
        __syncthreads();                  // h stores visible before t0's arrival
        unsigned gen = 0, old = 0;
        if (tid == 0) {
            gen = *bgen;                  // stable until leader publishes
            old = atom_add_acqrel(bcnt, 1u);
        }
        if (tid < 256)
            hseq[(size_t)(t * BSZ + B) * HC_ + hcg] = hlast;   // drains during wait
        if (tid == 0) {
            if (old == GCTAS - 1) {
                *bcnt = 0;                // ordered before gen by release below
                st_release(bgen, gen + 1);
            } else {
                while (ld_acquire(bgen) == gen) {}
            }
        }
        __syncthreads();
    }

    if (tid < 256) {
        hs_out[B * HC_ + hcg] = hlast;
        cs_out[B * HC_ + hcg] = cstate;
    }
}

#define RK_SMEM (512 * 64 * 4 + 16 * 32 * CPSTRIDE * 8)   // 131072 + 69632 = 200704

// ---------------------------------------------------------------------------
// Launch: sgemm(L0) -> rec(L0) -> sgemm(L1) -> rec(L1 -> d_out)
// ---------------------------------------------------------------------------
extern "C" void kernel_launch(void* const* d_in, const int* in_sizes, int n_in,
                              void* d_out, int out_size) {
    const float* x  = (const float*)d_in[0];
    const float* W0 = (const float*)d_in[1];
    const float* b0 = (const float*)d_in[2];
    const float* W1 = (const float*)d_in[3];
    const float* b1 = (const float*)d_in[4];
    const float* h0 = (const float*)d_in[5];
    const float* c0 = (const float*)d_in[6];

    float* out = (float*)d_out;                      // [T, BS, HC]
    float* hs  = out + (size_t)TT * BSZ * HC_;       // [L, BS, HC]
    float* cs  = hs + (size_t)2 * BSZ * HC_;         // [L, BS, HC]

    float* zptr = nullptr;
    float* hseq0 = nullptr;
    cudaGetSymbolAddress((void**)&zptr, g_z);
    cudaGetSymbolAddress((void**)&hseq0, g_hseq);

    static int smem_set = 0;
    if (!smem_set) {
        cudaFuncSetAttribute(lstm_rec, cudaFuncAttributeMaxDynamicSharedMemorySize, RK_SMEM);
        smem_set = 1;
    }

    dim3 ggrid(ZC_ / 128, MR / 128);

    // Layer 0
    sgemm_bias<<<ggrid, 256>>>(x, W0, b0, zptr);
    lstm_rec<<<RK_CTAS, RK_THR, RK_SMEM>>>(W0 + (size_t)IC_ * ZC_, h0, c0,
                                           hseq0, hs, cs);
    // Layer 1
    sgemm_bias<<<ggrid, 256>>>(hseq0, W1, b1, zptr);
    lstm_rec<<<RK_CTAS, RK_THR, RK_SMEM>>>(W1 + (size_t)HC_ * ZC_, h0 + HC_, c0 + HC_,
                                           out, hs + BSZ * HC_, cs + BSZ * HC_);
}

// round 11
// speedup vs baseline: 2.2025x; 1.1708x over previous
#include <cuda_runtime.h>
#include <cuda_bf16.h>
#include <cstdint>
#include <cstddef>

// Problem constants
#define TT   512
#define BSZ  64
#define IC_  512
#define HC_  512
#define ZC_  2048
#define MR   (TT*BSZ)
#define KBIG 1536          // 3 x 512 (hi/lo split passes folded into K)

#define RK_CTAS 128
#define RK_THR  512
#define NGRP    4
#define GCTAS   32

typedef unsigned long long ull;

// ---------------------------------------------------------------------------
// Static device scratch (no cudaMalloc allowed)
// ---------------------------------------------------------------------------
__device__ float g_z[(size_t)MR * ZC_];              // 256 MB
__device__ float g_hseq[(size_t)MR * HC_];           // 64 MB
__device__ float g_hg[2][NGRP][HC_][16];
__device__ unsigned g_bcnt[NGRP * 32];
__device__ unsigned g_bgen[NGRP * 32];
__device__ __nv_bfloat16 gAbig[(size_t)MR * KBIG];   // 96 MB: [Ah | Ah | Al]
__device__ __nv_bfloat16 gBbig[(size_t)ZC_ * KBIG];  // 6 MB:  [Wh | Wl | Wh], [n][k]

// ---------------------------------------------------------------------------
// f32x2 + sync helpers (R9-proven)
// ---------------------------------------------------------------------------
__device__ __forceinline__ ull pack2(float x, float y) {
    ull r; asm("mov.b64 %0, {%1, %2};" : "=l"(r) : "f"(x), "f"(y)); return r;
}
__device__ __forceinline__ void unpack2(ull v, float& x, float& y) {
    asm("mov.b64 {%0, %1}, %2;" : "=f"(x), "=f"(y) : "l"(v));
}
__device__ __forceinline__ void ffma2(ull& d, ull a, ull b) {
    asm("fma.rn.f32x2 %0, %1, %2, %0;" : "+l"(d) : "l"(a), "l"(b));
}
__device__ __forceinline__ void fadd2(ull& d, ull a) {
    asm("add.rn.f32x2 %0, %0, %1;" : "+l"(d) : "l"(a));
}
__device__ __forceinline__ unsigned atom_add_acqrel(unsigned* p, unsigned v) {
    unsigned old;
    asm volatile("atom.global.add.acq_rel.gpu.u32 %0, [%1], %2;"
                 : "=r"(old) : "l"(p), "r"(v) : "memory");
    return old;
}
__device__ __forceinline__ unsigned ld_acquire(const unsigned* p) {
    unsigned v;
    asm volatile("ld.global.acquire.gpu.u32 %0, [%1];" : "=r"(v) : "l"(p) : "memory");
    return v;
}
__device__ __forceinline__ void st_release(unsigned* p, unsigned v) {
    asm volatile("st.global.release.gpu.u32 [%0], %1;" :: "l"(p), "r"(v) : "memory");
}
__device__ __forceinline__ float sigf(float x) { return 1.0f / (1.0f + __expf(-x)); }
__device__ __forceinline__ float tanh_fast(float x) {
    float ax = fabsf(x);
    float e = __expf(-2.0f * ax);
    float r = (1.0f - e) / (1.0f + e);
    return copysignf(r, x);
}
__device__ __forceinline__ uint32_t smem_u32(const void* p) {
    uint32_t a;
    asm("{ .reg .u64 t; cvta.to.shared.u64 t, %1; cvt.u32.u64 %0, t; }" : "=r"(a) : "l"(p));
    return a;
}

// ---------------------------------------------------------------------------
// HMMA helpers (baseline PTX — no sm_103a-gated features)
// ---------------------------------------------------------------------------
__device__ __forceinline__ void ldsm_x4(uint32_t* r, uint32_t addr) {
    asm volatile("ldmatrix.sync.aligned.m8n8.x4.shared.b16 {%0,%1,%2,%3}, [%4];"
                 : "=r"(r[0]), "=r"(r[1]), "=r"(r[2]), "=r"(r[3]) : "r"(addr));
}
__device__ __forceinline__ void mma_bf16(float* d, const uint32_t* a, const uint32_t* b) {
    asm volatile(
        "mma.sync.aligned.m16n8k16.row.col.f32.bf16.bf16.f32 "
        "{%0,%1,%2,%3}, {%4,%5,%6,%7}, {%8,%9}, {%0,%1,%2,%3};"
        : "+f"(d[0]), "+f"(d[1]), "+f"(d[2]), "+f"(d[3])
        : "r"(a[0]), "r"(a[1]), "r"(a[2]), "r"(a[3]), "r"(b[0]), "r"(b[1]));
}

// ---------------------------------------------------------------------------
// Conversion kernels
// ---------------------------------------------------------------------------
__global__ __launch_bounds__(256) void conv_a(
        const float* __restrict__ A,               // [MR][512] fp32
        __nv_bfloat16* __restrict__ Abig) {        // [MR][1536]: [Ah|Ah|Al]
    size_t i = ((size_t)blockIdx.x * 256 + threadIdx.x) * 4;
    int m = (int)(i >> 9), k = (int)(i & 511);
    float4 v = *(const float4*)(A + i);
    __nv_bfloat16 h[4], l[4];
    const float* vf = (const float*)&v;
#pragma unroll
    for (int q = 0; q < 4; q++) {
        h[q] = __float2bfloat16(vf[q]);
        l[q] = __float2bfloat16(vf[q] - __bfloat162float(h[q]));
    }
    __nv_bfloat16* row = Abig + (size_t)m * KBIG;
    *(ull*)(row + k)        = *(const ull*)h;
    *(ull*)(row + 512 + k)  = *(const ull*)h;
    *(ull*)(row + 1024 + k) = *(const ull*)l;
}

__global__ __launch_bounds__(256) void conv_w(
        const float* __restrict__ W,               // rows 0..511 of [., 2048]
        __nv_bfloat16* __restrict__ Bbig) {        // [2048][1536]: [Wh|Wl|Wh]
    int idx = blockIdx.x * 256 + threadIdx.x;      // k*2048 + n (coalesced read)
    int k = idx >> 11, n = idx & 2047;
    float x = W[idx];
    __nv_bfloat16 h = __float2bfloat16(x);
    __nv_bfloat16 l = __float2bfloat16(x - __bfloat162float(h));
    __nv_bfloat16* row = Bbig + (size_t)n * KBIG;
    row[k]        = h;
    row[512 + k]  = l;
    row[1024 + k] = h;
}

// ---------------------------------------------------------------------------
// Phase 1: Z = Abig @ Bbig^T + bias (bf16 HMMA, fp32 accum).
// CTA 128x128, BK=32, 8 warps x (64m x 32n), mma m16n8k16, K=1536 (48 iters).
// Double-buffered padded smem (row stride 40 bf16 = 80 B, ldmatrix
// conflict-free), register prefetch (R9-proven loop skeleton).
// ---------------------------------------------------------------------------
#define ROWB 40                       // bf16 per smem row (32 data + 8 pad)
#define AS_BYTES (128 * ROWB * 2)     // 10240
#define STAGE_BYTES (2 * AS_BYTES)    // A + B
#define TCSMEM (2 * STAGE_BYTES)      // 40960

__global__ __launch_bounds__(256, 2) void sgemm_tc(
        const __nv_bfloat16* __restrict__ Abig,    // [MR][1536]
        const __nv_bfloat16* __restrict__ Bbig,    // [2048][1536]
        const float* __restrict__ bias,            // [2048]
        float* __restrict__ Z) {                   // [MR][2048]
    extern __shared__ char smem[];
    const uint32_t sbase = smem_u32(smem);
    const int tid = threadIdx.x;
    const int wid = tid >> 5, lane = tid & 31;
    const int m0 = blockIdx.y * 128;
    const int n0 = blockIdx.x * 128;
    const int m_warp = (wid & 1) * 64;
    const int n_warp = (wid >> 1) * 32;

    float acc[4][4][4];
#pragma unroll
    for (int i = 0; i < 4; i++)
#pragma unroll
        for (int j = 0; j < 4; j++)
#pragma unroll
            for (int q = 0; q < 4; q++) acc[i][j][q] = 0.f;

    // Staging map: 2 chunks of 16B each for A and B
    const int c0 = tid * 2;
    const int arow0 = c0 >> 2,      acol0 = (c0 & 3) * 8;
    const int arow1 = (c0 + 1) >> 2, acol1 = ((c0 + 1) & 3) * 8;

    // ldmatrix per-lane byte offsets
    const uint32_t aoff = ((lane & 15) * ROWB + (lane >> 4) * 8) * 2;
    const uint32_t boff = ((((lane >> 4) & 1) * 8 + (lane & 7)) * ROWB
                           + ((lane >> 3) & 1) * 8) * 2;

    // Prologue: load iter-0 chunks into registers
    ulonglong2 aPf0, aPf1, bPf0, bPf1;
    aPf0 = *(const ulonglong2*)(Abig + (size_t)(m0 + arow0) * KBIG + acol0);
    aPf1 = *(const ulonglong2*)(Abig + (size_t)(m0 + arow1) * KBIG + acol1);
    bPf0 = *(const ulonglong2*)(Bbig + (size_t)(n0 + arow0) * KBIG + acol0);
    bPf1 = *(const ulonglong2*)(Bbig + (size_t)(n0 + arow1) * KBIG + acol1);

    for (int it = 0; it < KBIG / 32; it++) {
        const int s = it & 1;
        char* As = smem + s * STAGE_BYTES;
        char* Bs = As + AS_BYTES;

        *(ulonglong2*)(As + arow0 * 80 + acol0 * 2) = aPf0;
        *(ulonglong2*)(As + arow1 * 80 + acol1 * 2) = aPf1;
        *(ulonglong2*)(Bs + arow0 * 80 + acol0 * 2) = bPf0;
        *(ulonglong2*)(Bs + arow1 * 80 + acol1 * 2) = bPf1;
        __syncthreads();

        if (it + 1 < KBIG / 32) {
            const int kb = (it + 1) * 32;
            aPf0 = *(const ulonglong2*)(Abig + (size_t)(m0 + arow0) * KBIG + kb + acol0);
            aPf1 = *(const ulonglong2*)(Abig + (size_t)(m0 + arow1) * KBIG + kb + acol1);
            bPf0 = *(const ulonglong2*)(Bbig + (size_t)(n0 + arow0) * KBIG + kb + acol0);
            bPf1 = *(const ulonglong2*)(Bbig + (size_t)(n0 + arow1) * KBIG + kb + acol1);
        }

        const uint32_t sA = sbase + s * STAGE_BYTES;
        const uint32_t sB = sA + AS_BYTES;
#pragma unroll
        for (int ks = 0; ks < 2; ks++) {
            uint32_t af[4][4], bf[2][4];
#pragma unroll
            for (int mi = 0; mi < 4; mi++)
                ldsm_x4(af[mi], sA + (m_warp + 16 * mi) * 80 + ks * 32 + aoff);
#pragma unroll
            for (int j2 = 0; j2 < 2; j2++)
                ldsm_x4(bf[j2], sB + (n_warp + 16 * j2) * 80 + ks * 32 + boff);
#pragma unroll
            for (int mi = 0; mi < 4; mi++)
#pragma unroll
                for (int nj = 0; nj < 4; nj++)
                    mma_bf16(acc[mi][nj], af[mi], &bf[nj >> 1][(nj & 1) * 2]);
        }
        __syncthreads();
    }

    // Epilogue: bias + store (float2 per fragment row)
#pragma unroll
    for (int mi = 0; mi < 4; mi++) {
        const int r0 = m0 + m_warp + 16 * mi + (lane >> 2);
#pragma unroll
        for (int nj = 0; nj < 4; nj++) {
            const int c = n0 + n_warp + 8 * nj + (lane & 3) * 2;
            float2 bv = *(const float2*)(bias + c);
            float2 o0 = make_float2(acc[mi][nj][0] + bv.x, acc[mi][nj][1] + bv.y);
            float2 o1 = make_float2(acc[mi][nj][2] + bv.x, acc[mi][nj][3] + bv.y);
            *(float2*)(Z + (size_t)r0 * ZC_ + c) = o0;
            *(float2*)(Z + (size_t)(r0 + 8) * ZC_ + c) = o1;
        }
    }
}

// ---------------------------------------------------------------------------
// Phase 2: persistent recurrence (R9-exact)
// ---------------------------------------------------------------------------
#define CPSTRIDE 17

__global__ __launch_bounds__(RK_THR, 1) void lstm_rec(
        const float* __restrict__ Wh,
        const float* __restrict__ h0l,
        const float* __restrict__ c0l,
        float* __restrict__ hseq,
        float* __restrict__ hs_out,
        float* __restrict__ cs_out) {
    extern __shared__ float smemf[];
    float* Wsm = smemf;
    ull*   Rsm = (ull*)(smemf + 512 * 64);

    const int tid  = threadIdx.x;
    const int cid  = blockIdx.x;
    const int grp  = cid & 3;
    const int cb   = cid >> 2;
    const int wid  = tid >> 5, lane = tid & 31;
    const int ch   = lane >> 2;
    const int b4   = (lane & 3) << 2;
    const int kbase = wid << 5;

    unsigned* bcnt = &g_bcnt[grp * 32];
    unsigned* bgen = &g_bgen[grp * 32];

    for (int idx = tid; idx < 512 * 64; idx += RK_THR) {
        int k = idx >> 6, c = idx & 63;
        int hcol = c >> 2, gate = c & 3;
        Wsm[idx] = Wh[(size_t)k * ZC_ + (size_t)gate * HC_ + cb * 16 + hcol];
    }

    const int fcol = tid & 15;
    const int fb   = tid >> 4;
    const int hcg  = cb * 16 + fcol;
    const int B    = grp * 16 + fb;
    float cstate = 0.f, hlast = 0.f;
    if (tid < 256) {
        cstate = c0l[hcg];
        hlast  = h0l[hcg];
        __stcg(&g_hg[0][grp][hcg][fb], hlast);
    }
    __syncthreads();
    if (tid == 0) {
        unsigned gen = *bgen;
        unsigned old = atom_add_acqrel(bcnt, 1u);
        if (old == GCTAS - 1) { *bcnt = 0; st_release(bgen, gen + 1); }
        else { while (ld_acquire(bgen) == gen) {} }
    }
    __syncthreads();

    for (int t = 0; t < TT; t++) {
        float z0 = 0.f, z1 = 0.f, z2 = 0.f, z3 = 0.f;
        if (tid < 256) {
            const float* zr = g_z + (size_t)(t * BSZ + B) * ZC_ + hcg;
            z0 = __ldcg(zr);
            z1 = __ldcg(zr + HC_);
            z2 = __ldcg(zr + 2 * HC_);
            z3 = __ldcg(zr + 3 * HC_);
        }

        const float* hb = &g_hg[t & 1][grp][0][0] + b4;
        ull acc[4][4];
#pragma unroll
        for (int b = 0; b < 4; b++)
#pragma unroll
            for (int q = 0; q < 4; q++) acc[b][q] = 0ull;

        float4 hA = __ldcg((const float4*)(hb + (kbase + 0) * 16));
        float4 hB = __ldcg((const float4*)(hb + (kbase + 1) * 16));
        float4 hC = __ldcg((const float4*)(hb + (kbase + 2) * 16));

#pragma unroll
        for (int i = 0; i < 32; i++) {
            float4 cur = hA;
            hA = hB; hB = hC;
            if (i < 29)
                hC = __ldcg((const float4*)(hb + (kbase + i + 3) * 16));

            const int k = kbase + i;
            const ulonglong2* wp = (const ulonglong2*)(Wsm + k * 64 + ch * 8);
            ulonglong2 w01 = wp[0], w23 = wp[1];
            ull hp[4];
            hp[0] = pack2(cur.x, cur.x);
            hp[1] = pack2(cur.y, cur.y);
            hp[2] = pack2(cur.z, cur.z);
            hp[3] = pack2(cur.w, cur.w);
#pragma unroll
            for (int b = 0; b < 4; b++) {
                ffma2(acc[b][0], hp[b], w01.x);
                ffma2(acc[b][1], hp[b], w01.y);
                ffma2(acc[b][2], hp[b], w23.x);
                ffma2(acc[b][3], hp[b], w23.y);
            }
        }

        {
            ull* base = Rsm + (size_t)wid * (32 * CPSTRIDE);
#pragma unroll
            for (int q = 0; q < 4; q++) {
                ull* row = base + (ch * 4 + q) * CPSTRIDE + b4;
                row[0] = acc[0][q];
                row[1] = acc[1][q];
                row[2] = acc[2][q];
                row[3] = acc[3][q];
            }
        }
        __syncthreads();

        if (tid < 256) {
            ull s0 = 0ull, s1 = 0ull;
            const ull* r0 = Rsm + (fcol * 2 + 0) * CPSTRIDE + fb;
            const ull* r1 = Rsm + (fcol * 2 + 1) * CPSTRIDE + fb;
#pragma unroll
            for (int kg = 0; kg < 16; kg++) {
                fadd2(s0, r0[kg * 32 * CPSTRIDE]);
                fadd2(s1, r1[kg * 32 * CPSTRIDE]);
            }
            float f, i, o, g;
            unpack2(s0, f, i);
            unpack2(s1, o, g);
            f += z0; i += z1; o += z2; g += z3;
            f = sigf(f + 1.0f);
            i = sigf(i);
            o = sigf(o);
            g = tanh_fast(g);
            cstate = cstate * f + g * i;
            hlast = o * tanh_fast(cstate);

            __stcg(&g_hg[(t + 1) & 1][grp][hcg][fb], hlast);
        }

        __syncthreads();
        unsigned gen = 0, old = 0;
        if (tid == 0) {
            gen = *bgen;
            old = atom_add_acqrel(bcnt, 1u);
        }
        if (tid < 256)
            hseq[(size_t)(t * BSZ + B) * HC_ + hcg] = hlast;
        if (tid == 0) {
            if (old == GCTAS - 1) { *bcnt = 0; st_release(bgen, gen + 1); }
            else { while (ld_acquire(bgen) == gen) {} }
        }
        __syncthreads();
    }

    if (tid < 256) {
        hs_out[B * HC_ + hcg] = hlast;
        cs_out[B * HC_ + hcg] = cstate;
    }
}

#define RK_SMEM (512 * 64 * 4 + 16 * 32 * CPSTRIDE * 8)

// ---------------------------------------------------------------------------
// Launch: conv -> sgemm_tc -> rec, per layer
// ---------------------------------------------------------------------------
extern "C" void kernel_launch(void* const* d_in, const int* in_sizes, int n_in,
                              void* d_out, int out_size) {
    const float* x  = (const float*)d_in[0];
    const float* W0 = (const float*)d_in[1];
    const float* b0 = (const float*)d_in[2];
    const float* W1 = (const float*)d_in[3];
    const float* b1 = (const float*)d_in[4];
    const float* h0 = (const float*)d_in[5];
    const float* c0 = (const float*)d_in[6];

    float* out = (float*)d_out;
    float* hs  = out + (size_t)TT * BSZ * HC_;
    float* cs  = hs + (size_t)2 * BSZ * HC_;

    float *zptr = nullptr, *hseq0 = nullptr;
    __nv_bfloat16 *abig = nullptr, *bbig = nullptr;
    cudaGetSymbolAddress((void**)&zptr, g_z);
    cudaGetSymbolAddress((void**)&hseq0, g_hseq);
    cudaGetSymbolAddress((void**)&abig, gAbig);
    cudaGetSymbolAddress((void**)&bbig, gBbig);

    static int attr_set = 0;
    if (!attr_set) {
        cudaFuncSetAttribute(lstm_rec, cudaFuncAttributeMaxDynamicSharedMemorySize, RK_SMEM);
        cudaFuncSetAttribute(sgemm_tc, cudaFuncAttributeMaxDynamicSharedMemorySize, TCSMEM);
        attr_set = 1;
    }

    dim3 tgrid(ZC_ / 128, MR / 128);

    // Layer 0
    conv_w<<<(512 * ZC_) / 256, 256>>>(W0, bbig);
    conv_a<<<(MR * IC_) / 1024, 256>>>(x, abig);
    sgemm_tc<<<tgrid, 256, TCSMEM>>>(abig, bbig, b0, zptr);
    lstm_rec<<<RK_CTAS, RK_THR, RK_SMEM>>>(W0 + (size_t)IC_ * ZC_, h0, c0,
                                           hseq0, hs, cs);
    // Layer 1
    conv_w<<<(512 * ZC_) / 256, 256>>>(W1, bbig);
    conv_a<<<(MR * HC_) / 1024, 256>>>(hseq0, abig);
    sgemm_tc<<<tgrid, 256, TCSMEM>>>(abig, bbig, b1, zptr);
    lstm_rec<<<RK_CTAS, RK_THR, RK_SMEM>>>(W1 + (size_t)HC_ * ZC_, h0 + HC_, c0 + HC_,
                                           out, hs + BSZ * HC_, cs + BSZ * HC_);
}

// round 12
// speedup vs baseline: 2.7320x; 1.2404x over previous
#include <cuda_runtime.h>
#include <cuda_bf16.h>
#include <cstdint>
#include <cstddef>

// Problem constants
#define TT   512
#define BSZ  64
#define IC_  512
#define HC_  512
#define ZC_  2048
#define MR   (TT*BSZ)
#define KBIG 1536

#define RK_CTAS 128
#define RK_THR  512
#define NGRP    4
#define GCTAS   32

typedef unsigned long long ull;

// ---------------------------------------------------------------------------
// Static device scratch
// ---------------------------------------------------------------------------
__device__ float g_z[(size_t)MR * ZC_];              // 256 MB
__device__ float g_hseq[(size_t)MR * HC_];           // 64 MB
__device__ __nv_bfloat16 g_hbf[2][NGRP][2][16][HC_]; // h as bf16 hi/lo, [b][k]
__device__ unsigned g_bcnt[NGRP * 32];
__device__ unsigned g_bgen[NGRP * 32];
__device__ __nv_bfloat16 gAbig[(size_t)MR * KBIG];   // 96 MB: [Ah | Ah | Al]
__device__ __nv_bfloat16 gBbig[(size_t)ZC_ * KBIG];  // 6 MB:  [Wh | Wl | Wh]

// ---------------------------------------------------------------------------
// Helpers
// ---------------------------------------------------------------------------
__device__ __forceinline__ unsigned atom_add_acqrel(unsigned* p, unsigned v) {
    unsigned old;
    asm volatile("atom.global.add.acq_rel.gpu.u32 %0, [%1], %2;"
                 : "=r"(old) : "l"(p), "r"(v) : "memory");
    return old;
}
__device__ __forceinline__ unsigned ld_acquire(const unsigned* p) {
    unsigned v;
    asm volatile("ld.global.acquire.gpu.u32 %0, [%1];" : "=r"(v) : "l"(p) : "memory");
    return v;
}
__device__ __forceinline__ void st_release(unsigned* p, unsigned v) {
    asm volatile("st.global.release.gpu.u32 [%0], %1;" :: "l"(p), "r"(v) : "memory");
}
__device__ __forceinline__ float sigf(float x) { return 1.0f / (1.0f + __expf(-x)); }
__device__ __forceinline__ float tanh_fast(float x) {
    float ax = fabsf(x);
    float e = __expf(-2.0f * ax);
    float r = (1.0f - e) / (1.0f + e);
    return copysignf(r, x);
}
__device__ __forceinline__ uint32_t smem_u32(const void* p) {
    uint32_t a;
    asm("{ .reg .u64 t; cvta.to.shared.u64 t, %1; cvt.u32.u64 %0, t; }" : "=r"(a) : "l"(p));
    return a;
}
__device__ __forceinline__ void ldsm_x4(uint32_t* r, uint32_t addr) {
    asm volatile("ldmatrix.sync.aligned.m8n8.x4.shared.b16 {%0,%1,%2,%3}, [%4];"
                 : "=r"(r[0]), "=r"(r[1]), "=r"(r[2]), "=r"(r[3]) : "r"(addr));
}
__device__ __forceinline__ void mma_bf16(float* d, const uint32_t* a, const uint32_t* b) {
    asm volatile(
        "mma.sync.aligned.m16n8k16.row.col.f32.bf16.bf16.f32 "
        "{%0,%1,%2,%3}, {%4,%5,%6,%7}, {%8,%9}, {%0,%1,%2,%3};"
        : "+f"(d[0]), "+f"(d[1]), "+f"(d[2]), "+f"(d[3])
        : "r"(a[0]), "r"(a[1]), "r"(a[2]), "r"(a[3]), "r"(b[0]), "r"(b[1]));
}

// ---------------------------------------------------------------------------
// Conversion kernels (R11-exact)
// ---------------------------------------------------------------------------
__global__ __launch_bounds__(256) void conv_a(
        const float* __restrict__ A, __nv_bfloat16* __restrict__ Abig) {
    size_t i = ((size_t)blockIdx.x * 256 + threadIdx.x) * 4;
    int m = (int)(i >> 9), k = (int)(i & 511);
    float4 v = *(const float4*)(A + i);
    __nv_bfloat16 h[4], l[4];
    const float* vf = (const float*)&v;
#pragma unroll
    for (int q = 0; q < 4; q++) {
        h[q] = __float2bfloat16(vf[q]);
        l[q] = __float2bfloat16(vf[q] - __bfloat162float(h[q]));
    }
    __nv_bfloat16* row = Abig + (size_t)m * KBIG;
    *(ull*)(row + k)        = *(const ull*)h;
    *(ull*)(row + 512 + k)  = *(const ull*)h;
    *(ull*)(row + 1024 + k) = *(const ull*)l;
}

__global__ __launch_bounds__(256) void conv_w(
        const float* __restrict__ W, __nv_bfloat16* __restrict__ Bbig) {
    int idx = blockIdx.x * 256 + threadIdx.x;
    int k = idx >> 11, n = idx & 2047;
    float x = W[idx];
    __nv_bfloat16 h = __float2bfloat16(x);
    __nv_bfloat16 l = __float2bfloat16(x - __bfloat162float(h));
    __nv_bfloat16* row = Bbig + (size_t)n * KBIG;
    row[k]        = h;
    row[512 + k]  = l;
    row[1024 + k] = h;
}

// ---------------------------------------------------------------------------
// Phase 1: HMMA GEMM (R11-exact, passed @ ~0.7 ms/launch)
// ---------------------------------------------------------------------------
#define ROWB 40
#define AS_BYTES (128 * ROWB * 2)
#define STAGE_BYTES (2 * AS_BYTES)
#define TCSMEM (2 * STAGE_BYTES)

__global__ __launch_bounds__(256, 2) void sgemm_tc(
        const __nv_bfloat16* __restrict__ Abig,
        const __nv_bfloat16* __restrict__ Bbig,
        const float* __restrict__ bias,
        float* __restrict__ Z) {
    extern __shared__ char smem[];
    const uint32_t sbase = smem_u32(smem);
    const int tid = threadIdx.x;
    const int wid = tid >> 5, lane = tid & 31;
    const int m0 = blockIdx.y * 128;
    const int n0 = blockIdx.x * 128;
    const int m_warp = (wid & 1) * 64;
    const int n_warp = (wid >> 1) * 32;

    float acc[4][4][4];
#pragma unroll
    for (int i = 0; i < 4; i++)
#pragma unroll
        for (int j = 0; j < 4; j++)
#pragma unroll
            for (int q = 0; q < 4; q++) acc[i][j][q] = 0.f;

    const int c0 = tid * 2;
    const int arow0 = c0 >> 2,       acol0 = (c0 & 3) * 8;
    const int arow1 = (c0 + 1) >> 2, acol1 = ((c0 + 1) & 3) * 8;

    const uint32_t aoff = ((lane & 15) * ROWB + (lane >> 4) * 8) * 2;
    const uint32_t boff = ((((lane >> 4) & 1) * 8 + (lane & 7)) * ROWB
                           + ((lane >> 3) & 1) * 8) * 2;

    ulonglong2 aPf0, aPf1, bPf0, bPf1;
    aPf0 = *(const ulonglong2*)(Abig + (size_t)(m0 + arow0) * KBIG + acol0);
    aPf1 = *(const ulonglong2*)(Abig + (size_t)(m0 + arow1) * KBIG + acol1);
    bPf0 = *(const ulonglong2*)(Bbig + (size_t)(n0 + arow0) * KBIG + acol0);
    bPf1 = *(const ulonglong2*)(Bbig + (size_t)(n0 + arow1) * KBIG + acol1);

    for (int it = 0; it < KBIG / 32; it++) {
        const int s = it & 1;
        char* As = smem + s * STAGE_BYTES;
        char* Bs = As + AS_BYTES;

        *(ulonglong2*)(As + arow0 * 80 + acol0 * 2) = aPf0;
        *(ulonglong2*)(As + arow1 * 80 + acol1 * 2) = aPf1;
        *(ulonglong2*)(Bs + arow0 * 80 + acol0 * 2) = bPf0;
        *(ulonglong2*)(Bs + arow1 * 80 + acol1 * 2) = bPf1;
        __syncthreads();

        if (it + 1 < KBIG / 32) {
            const int kb = (it + 1) * 32;
            aPf0 = *(const ulonglong2*)(Abig + (size_t)(m0 + arow0) * KBIG + kb + acol0);
            aPf1 = *(const ulonglong2*)(Abig + (size_t)(m0 + arow1) * KBIG + kb + acol1);
            bPf0 = *(const ulonglong2*)(Bbig + (size_t)(n0 + arow0) * KBIG + kb + acol0);
            bPf1 = *(const ulonglong2*)(Bbig + (size_t)(n0 + arow1) * KBIG + kb + acol1);
        }

        const uint32_t sA = sbase + s * STAGE_BYTES;
        const uint32_t sB = sA + AS_BYTES;
#pragma unroll
        for (int ks = 0; ks < 2; ks++) {
            uint32_t af[4][4], bf[2][4];
#pragma unroll
            for (int mi = 0; mi < 4; mi++)
                ldsm_x4(af[mi], sA + (m_warp + 16 * mi) * 80 + ks * 32 + aoff);
#pragma unroll
            for (int j2 = 0; j2 < 2; j2++)
                ldsm_x4(bf[j2], sB + (n_warp + 16 * j2) * 80 + ks * 32 + boff);
#pragma unroll
            for (int mi = 0; mi < 4; mi++)
#pragma unroll
                for (int nj = 0; nj < 4; nj++)
                    mma_bf16(acc[mi][nj], af[mi], &bf[nj >> 1][(nj & 1) * 2]);
        }
        __syncthreads();
    }

#pragma unroll
    for (int mi = 0; mi < 4; mi++) {
        const int r0 = m0 + m_warp + 16 * mi + (lane >> 2);
#pragma unroll
        for (int nj = 0; nj < 4; nj++) {
            const int c = n0 + n_warp + 8 * nj + (lane & 3) * 2;
            float2 bv = *(const float2*)(bias + c);
            float2 o0 = make_float2(acc[mi][nj][0] + bv.x, acc[mi][nj][1] + bv.y);
            float2 o1 = make_float2(acc[mi][nj][2] + bv.x, acc[mi][nj][3] + bv.y);
            *(float2*)(Z + (size_t)r0 * ZC_ + c) = o0;
            *(float2*)(Z + (size_t)(r0 + 8) * ZC_ + c) = o1;
        }
    }
}

// ---------------------------------------------------------------------------
// Phase 2: persistent recurrence on HMMA (bf16 hi/lo split).
// CTA: 16 batch x 64 gate-cols, k=512. W in smem [64 rows][Wh(512)|Wl(512)]
// bf16, row stride 1032 bf16 (2064 B, odd 16B multiple: ldmatrix-safe).
// h staged per step: [hh|hl][16 b][512 k] bf16, row stride 520 (1040 B).
// 16 warps = 4 k-splits x 4 n-pairs; per warp 8 kt-iters x (4 ldsm + 6 mma):
//   acc += hh*Wh + hl*Wh + hh*Wl.
// 4-way k-reduce via smem; finalize/gates/sync = R9-proven code.
// ---------------------------------------------------------------------------
#define WROW   2064                       // W smem row bytes
#define AROW   1040                       // A smem row bytes
#define SM_W   (64 * WROW)                // 132096
#define SM_AHH SM_W                       // 16*1040 = 16640
#define SM_AHL (SM_W + 16640)
#define SM_R   (SM_W + 2 * 16640)        // partials (float)
#define RK_SMEM (SM_R + 4 * 64 * 17 * 4)  // 165376 + 17408 = 182784

__global__ __launch_bounds__(RK_THR, 1) void lstm_rec(
        const float* __restrict__ Wh,     // [512, 2048] recurrent rows of W
        const float* __restrict__ h0l,
        const float* __restrict__ c0l,
        float* __restrict__ hseq,
        float* __restrict__ hs_out,
        float* __restrict__ cs_out) {
    extern __shared__ char smem[];
    const uint32_t sb = smem_u32(smem);
    float* Rsm = (float*)(smem + SM_R);

    const int tid  = threadIdx.x;
    const int cid  = blockIdx.x;
    const int grp  = cid & 3;
    const int cb   = cid >> 2;
    const int wid  = tid >> 5, lane = tid & 31;
    const int ks   = wid >> 2;            // k-split 0..3 (8 kt-tiles each)
    const int nw   = wid & 3;             // n-pair 0..3 (16 gate-cols each)

    unsigned* bcnt = &g_bcnt[grp * 32];
    unsigned* bgen = &g_bgen[grp * 32];

    // Build W smem: row c (= hcol*4 + gate): [Wh | Wl] bf16
    for (int idx = tid; idx < 64 * 512; idx += RK_THR) {
        int c = idx >> 9, k = idx & 511;
        int hcol = c >> 2, gate = c & 3;
        float x = Wh[(size_t)k * ZC_ + (size_t)gate * HC_ + cb * 16 + hcol];
        __nv_bfloat16 h = __float2bfloat16(x);
        __nv_bfloat16 l = __float2bfloat16(x - __bfloat162float(h));
        *(__nv_bfloat16*)(smem + c * WROW + k * 2)        = h;
        *(__nv_bfloat16*)(smem + c * WROW + 1024 + k * 2) = l;
    }

    // ldmatrix per-lane offsets (R11-verified mapping)
    const uint32_t aoff = ((lane & 15) * 520 + (lane >> 4) * 8) * 2;
    const uint32_t boff = ((((lane >> 4) & 1) * 8 + (lane & 7)) * 1032
                           + ((lane >> 3) & 1) * 8) * 2;
    const uint32_t sBrow = sb + nw * 16 * WROW;

    // Finalizer identity
    const int fcol = tid & 15;
    const int fb   = tid >> 4;
    const int hcg  = cb * 16 + fcol;
    const int B    = grp * 16 + fb;
    float cstate = 0.f, hlast = 0.f;
    if (tid < 256) {
        cstate = c0l[hcg];
        hlast  = h0l[hcg];
        __nv_bfloat16 hh = __float2bfloat16(hlast);
        __nv_bfloat16 hl = __float2bfloat16(hlast - __bfloat162float(hh));
        g_hbf[0][grp][0][fb][hcg] = hh;
        g_hbf[0][grp][1][fb][hcg] = hl;
    }
    __syncthreads();
    if (tid == 0) {
        unsigned gen = *bgen;
        unsigned old = atom_add_acqrel(bcnt, 1u);
        if (old == GCTAS - 1) { *bcnt = 0; st_release(bgen, gen + 1); }
        else { while (ld_acquire(bgen) == gen) {} }
    }
    __syncthreads();

    for (int t = 0; t < TT; t++) {
        // z prefetch (finalizers)
        float z0 = 0.f, z1 = 0.f, z2 = 0.f, z3 = 0.f;
        if (tid < 256) {
            const float* zr = g_z + (size_t)(t * BSZ + B) * ZC_ + hcg;
            z0 = __ldcg(zr);
            z1 = __ldcg(zr + HC_);
            z2 = __ldcg(zr + 2 * HC_);
            z3 = __ldcg(zr + 3 * HC_);
        }

        // Stage h tile: 32 KB (hi then lo), coalesced 16B chunks
        {
            const __nv_bfloat16* hsrc = &g_hbf[t & 1][grp][0][0][0];
#pragma unroll
            for (int j = 0; j < 4; j++) {
                int c = tid + j * 512;           // 2048 chunks of 16B
                int part = c >> 10, rem = c & 1023;
                int row = rem >> 6, off = rem & 63;
                ulonglong2 v = __ldcg((const ulonglong2*)
                    (hsrc + (size_t)part * 8192 + row * 512 + off * 8));
                *(ulonglong2*)(smem + SM_AHH + part * 16640 + row * AROW + off * 16) = v;
            }
        }
        __syncthreads();

        // GEMM: acc = hh*Wh + hl*Wh + hh*Wl over this warp's k-slice
        float acc[2][4];
#pragma unroll
        for (int nt = 0; nt < 2; nt++)
#pragma unroll
            for (int q = 0; q < 4; q++) acc[nt][q] = 0.f;

#pragma unroll
        for (int k8 = 0; k8 < 8; k8++) {
            const int kt = ks * 8 + k8;
            uint32_t ahh[4], ahl[4], bh[4], bl[4];
            ldsm_x4(ahh, sb + SM_AHH + kt * 32 + aoff);
            ldsm_x4(ahl, sb + SM_AHL + kt * 32 + aoff);
            ldsm_x4(bh, sBrow + kt * 32 + boff);
            ldsm_x4(bl, sBrow + 1024 + kt * 32 + boff);
            mma_bf16(acc[0], ahh, &bh[0]);
            mma_bf16(acc[1], ahh, &bh[2]);
            mma_bf16(acc[0], ahl, &bh[0]);
            mma_bf16(acc[1], ahl, &bh[2]);
            mma_bf16(acc[0], ahh, &bl[0]);
            mma_bf16(acc[1], ahh, &bl[2]);
        }

        // Store partials: Rsm[(ks*64 + gc)*17 + b]
#pragma unroll
        for (int nt = 0; nt < 2; nt++) {
            int gc = nw * 16 + nt * 8 + (lane & 3) * 2;
            int b = lane >> 2;
            float* base = Rsm + (ks * 64 + gc) * 17;
            base[b]          = acc[nt][0];
            base[17 + b]     = acc[nt][1];
            base[b + 8]      = acc[nt][2];
            base[17 + b + 8] = acc[nt][3];
        }
        __syncthreads();

        // Finalize: 4-way k-reduce, gates, state update
        if (tid < 256) {
            float f = z0, i = z1, o = z2, g = z3;
#pragma unroll
            for (int q = 0; q < 4; q++) {
                const float* r = Rsm + (q * 64 + fcol * 4) * 17 + fb;
                f += r[0];
                i += r[17];
                o += r[34];
                g += r[51];
            }
            f = sigf(f + 1.0f);
            i = sigf(i);
            o = sigf(o);
            g = tanh_fast(g);
            cstate = cstate * f + g * i;
            hlast = o * tanh_fast(cstate);

            __nv_bfloat16 hh = __float2bfloat16(hlast);
            __nv_bfloat16 hl = __float2bfloat16(hlast - __bfloat162float(hh));
            g_hbf[(t + 1) & 1][grp][0][fb][hcg] = hh;
            g_hbf[(t + 1) & 1][grp][1][fb][hcg] = hl;
        }

        __syncthreads();
        unsigned gen = 0, old = 0;
        if (tid == 0) {
            gen = *bgen;
            old = atom_add_acqrel(bcnt, 1u);
        }
        if (tid < 256)
            hseq[(size_t)(t * BSZ + B) * HC_ + hcg] = hlast;
        if (tid == 0) {
            if (old == GCTAS - 1) { *bcnt = 0; st_release(bgen, gen + 1); }
            else { while (ld_acquire(bgen) == gen) {} }
        }
        __syncthreads();
    }

    if (tid < 256) {
        hs_out[B * HC_ + hcg] = hlast;
        cs_out[B * HC_ + hcg] = cstate;
    }
}

// ---------------------------------------------------------------------------
// Launch
// ---------------------------------------------------------------------------
extern "C" void kernel_launch(void* const* d_in, const int* in_sizes, int n_in,
                              void* d_out, int out_size) {
    const float* x  = (const float*)d_in[0];
    const float* W0 = (const float*)d_in[1];
    const float* b0 = (const float*)d_in[2];
    const float* W1 = (const float*)d_in[3];
    const float* b1 = (const float*)d_in[4];
    const float* h0 = (const float*)d_in[5];
    const float* c0 = (const float*)d_in[6];

    float* out = (float*)d_out;
    float* hs  = out + (size_t)TT * BSZ * HC_;
    float* cs  = hs + (size_t)2 * BSZ * HC_;

    float *zptr = nullptr, *hseq0 = nullptr;
    __nv_bfloat16 *abig = nullptr, *bbig = nullptr;
    cudaGetSymbolAddress((void**)&zptr, g_z);
    cudaGetSymbolAddress((void**)&hseq0, g_hseq);
    cudaGetSymbolAddress((void**)&abig, gAbig);
    cudaGetSymbolAddress((void**)&bbig, gBbig);

    static int attr_set = 0;
    if (!attr_set) {
        cudaFuncSetAttribute(lstm_rec, cudaFuncAttributeMaxDynamicSharedMemorySize, RK_SMEM);
        cudaFuncSetAttribute(sgemm_tc, cudaFuncAttributeMaxDynamicSharedMemorySize, TCSMEM);
        attr_set = 1;
    }

    dim3 tgrid(ZC_ / 128, MR / 128);

    // Layer 0
    conv_w<<<(512 * ZC_) / 256, 256>>>(W0, bbig);
    conv_a<<<(MR * IC_) / 1024, 256>>>(x, abig);
    sgemm_tc<<<tgrid, 256, TCSMEM>>>(abig, bbig, b0, zptr);
    lstm_rec<<<RK_CTAS, RK_THR, RK_SMEM>>>(W0 + (size_t)IC_ * ZC_, h0, c0,
                                           hseq0, hs, cs);
    // Layer 1
    conv_w<<<(512 * ZC_) / 256, 256>>>(W1, bbig);
    conv_a<<<(MR * HC_) / 1024, 256>>>(hseq0, abig);
    sgemm_tc<<<tgrid, 256, TCSMEM>>>(abig, bbig, b1, zptr);
    lstm_rec<<<RK_CTAS, RK_THR, RK_SMEM>>>(W1 + (size_t)HC_ * ZC_, h0 + HC_, c0 + HC_,
                                           out, hs + BSZ * HC_, cs + BSZ * HC_);
}

// round 13
// speedup vs baseline: 3.1860x; 1.1662x over previous
#include <cuda_runtime.h>
#include <cuda_bf16.h>
#include <cstdint>
#include <cstddef>

// Problem constants
#define TT   512
#define BSZ  64
#define IC_  512
#define HC_  512
#define ZC_  2048
#define MR   (TT*BSZ)
#define KBIG 1536

#define RK_CTAS 128
#define RK_THR  512
#define NGRP    4
#define GCTAS   32

typedef unsigned long long ull;

// ---------------------------------------------------------------------------
// Static device scratch
// ---------------------------------------------------------------------------
__device__ float g_z[(size_t)MR * ZC_];              // 256 MB
__device__ float g_hseq[(size_t)MR * HC_];           // 64 MB
__device__ __nv_bfloat16 g_hbf[2][NGRP][2][16][HC_]; // h as bf16 hi/lo, [b][k]
__device__ unsigned g_bcnt[NGRP * 32];               // init-rendezvous counters
__device__ unsigned g_bgen[NGRP * 32];
__device__ unsigned g_mono[NGRP * 32];               // monotonic step counters
__device__ __nv_bfloat16 gAbig[(size_t)MR * KBIG];   // 96 MB: [Ah | Ah | Al]
__device__ __nv_bfloat16 gBbig[(size_t)ZC_ * KBIG];  // 6 MB:  [Wh | Wl | Wh]

// ---------------------------------------------------------------------------
// Helpers
// ---------------------------------------------------------------------------
__device__ __forceinline__ unsigned atom_add_acqrel(unsigned* p, unsigned v) {
    unsigned old;
    asm volatile("atom.global.add.acq_rel.gpu.u32 %0, [%1], %2;"
                 : "=r"(old) : "l"(p), "r"(v) : "memory");
    return old;
}
__device__ __forceinline__ void red_add_release(unsigned* p, unsigned v) {
    asm volatile("red.global.add.release.gpu.u32 [%0], %1;" :: "l"(p), "r"(v) : "memory");
}
__device__ __forceinline__ unsigned ld_acquire(const unsigned* p) {
    unsigned v;
    asm volatile("ld.global.acquire.gpu.u32 %0, [%1];" : "=r"(v) : "l"(p) : "memory");
    return v;
}
__device__ __forceinline__ void st_release(unsigned* p, unsigned v) {
    asm volatile("st.global.release.gpu.u32 [%0], %1;" :: "l"(p), "r"(v) : "memory");
}
__device__ __forceinline__ float sigf(float x) { return 1.0f / (1.0f + __expf(-x)); }
__device__ __forceinline__ float tanh_fast(float x) {
    float ax = fabsf(x);
    float e = __expf(-2.0f * ax);
    float r = (1.0f - e) / (1.0f + e);
    return copysignf(r, x);
}
__device__ __forceinline__ uint32_t smem_u32(const void* p) {
    uint32_t a;
    asm("{ .reg .u64 t; cvta.to.shared.u64 t, %1; cvt.u32.u64 %0, t; }" : "=r"(a) : "l"(p));
    return a;
}
__device__ __forceinline__ void ldsm_x4(uint32_t* r, uint32_t addr) {
    asm volatile("ldmatrix.sync.aligned.m8n8.x4.shared.b16 {%0,%1,%2,%3}, [%4];"
                 : "=r"(r[0]), "=r"(r[1]), "=r"(r[2]), "=r"(r[3]) : "r"(addr));
}
__device__ __forceinline__ void mma_bf16(float* d, const uint32_t* a, const uint32_t* b) {
    asm volatile(
        "mma.sync.aligned.m16n8k16.row.col.f32.bf16.bf16.f32 "
        "{%0,%1,%2,%3}, {%4,%5,%6,%7}, {%8,%9}, {%0,%1,%2,%3};"
        : "+f"(d[0]), "+f"(d[1]), "+f"(d[2]), "+f"(d[3])
        : "r"(a[0]), "r"(a[1]), "r"(a[2]), "r"(a[3]), "r"(b[0]), "r"(b[1]));
}

// ---------------------------------------------------------------------------
// Conversion kernels (R11-exact)
// ---------------------------------------------------------------------------
__global__ __launch_bounds__(256) void conv_a(
        const float* __restrict__ A, __nv_bfloat16* __restrict__ Abig) {
    size_t i = ((size_t)blockIdx.x * 256 + threadIdx.x) * 4;
    int m = (int)(i >> 9), k = (int)(i & 511);
    float4 v = *(const float4*)(A + i);
    __nv_bfloat16 h[4], l[4];
    const float* vf = (const float*)&v;
#pragma unroll
    for (int q = 0; q < 4; q++) {
        h[q] = __float2bfloat16(vf[q]);
        l[q] = __float2bfloat16(vf[q] - __bfloat162float(h[q]));
    }
    __nv_bfloat16* row = Abig + (size_t)m * KBIG;
    *(ull*)(row + k)        = *(const ull*)h;
    *(ull*)(row + 512 + k)  = *(const ull*)h;
    *(ull*)(row + 1024 + k) = *(const ull*)l;
}

__global__ __launch_bounds__(256) void conv_w(
        const float* __restrict__ W, __nv_bfloat16* __restrict__ Bbig) {
    int idx = blockIdx.x * 256 + threadIdx.x;
    int k = idx >> 11, n = idx & 2047;
    float x = W[idx];
    __nv_bfloat16 h = __float2bfloat16(x);
    __nv_bfloat16 l = __float2bfloat16(x - __bfloat162float(h));
    __nv_bfloat16* row = Bbig + (size_t)n * KBIG;
    row[k]        = h;
    row[512 + k]  = l;
    row[1024 + k] = h;
}

// ---------------------------------------------------------------------------
// Phase 1: HMMA GEMM (R11/R12-exact)
// ---------------------------------------------------------------------------
#define ROWB 40
#define AS_BYTES (128 * ROWB * 2)
#define STAGE_BYTES (2 * AS_BYTES)
#define TCSMEM (2 * STAGE_BYTES)

__global__ __launch_bounds__(256, 2) void sgemm_tc(
        const __nv_bfloat16* __restrict__ Abig,
        const __nv_bfloat16* __restrict__ Bbig,
        const float* __restrict__ bias,
        float* __restrict__ Z) {
    extern __shared__ char smem[];
    const uint32_t sbase = smem_u32(smem);
    const int tid = threadIdx.x;
    const int wid = tid >> 5, lane = tid & 31;
    const int m0 = blockIdx.y * 128;
    const int n0 = blockIdx.x * 128;
    const int m_warp = (wid & 1) * 64;
    const int n_warp = (wid >> 1) * 32;

    float acc[4][4][4];
#pragma unroll
    for (int i = 0; i < 4; i++)
#pragma unroll
        for (int j = 0; j < 4; j++)
#pragma unroll
            for (int q = 0; q < 4; q++) acc[i][j][q] = 0.f;

    const int c0 = tid * 2;
    const int arow0 = c0 >> 2,       acol0 = (c0 & 3) * 8;
    const int arow1 = (c0 + 1) >> 2, acol1 = ((c0 + 1) & 3) * 8;

    const uint32_t aoff = ((lane & 15) * ROWB + (lane >> 4) * 8) * 2;
    const uint32_t boff = ((((lane >> 4) & 1) * 8 + (lane & 7)) * ROWB
                           + ((lane >> 3) & 1) * 8) * 2;

    ulonglong2 aPf0, aPf1, bPf0, bPf1;
    aPf0 = *(const ulonglong2*)(Abig + (size_t)(m0 + arow0) * KBIG + acol0);
    aPf1 = *(const ulonglong2*)(Abig + (size_t)(m0 + arow1) * KBIG + acol1);
    bPf0 = *(const ulonglong2*)(Bbig + (size_t)(n0 + arow0) * KBIG + acol0);
    bPf1 = *(const ulonglong2*)(Bbig + (size_t)(n0 + arow1) * KBIG + acol1);

    for (int it = 0; it < KBIG / 32; it++) {
        const int s = it & 1;
        char* As = smem + s * STAGE_BYTES;
        char* Bs = As + AS_BYTES;

        *(ulonglong2*)(As + arow0 * 80 + acol0 * 2) = aPf0;
        *(ulonglong2*)(As + arow1 * 80 + acol1 * 2) = aPf1;
        *(ulonglong2*)(Bs + arow0 * 80 + acol0 * 2) = bPf0;
        *(ulonglong2*)(Bs + arow1 * 80 + acol1 * 2) = bPf1;
        __syncthreads();

        if (it + 1 < KBIG / 32) {
            const int kb = (it + 1) * 32;
            aPf0 = *(const ulonglong2*)(Abig + (size_t)(m0 + arow0) * KBIG + kb + acol0);
            aPf1 = *(const ulonglong2*)(Abig + (size_t)(m0 + arow1) * KBIG + kb + acol1);
            bPf0 = *(const ulonglong2*)(Bbig + (size_t)(n0 + arow0) * KBIG + kb + acol0);
            bPf1 = *(const ulonglong2*)(Bbig + (size_t)(n0 + arow1) * KBIG + kb + acol1);
        }

        const uint32_t sA = sbase + s * STAGE_BYTES;
        const uint32_t sB = sA + AS_BYTES;
#pragma unroll
        for (int ks = 0; ks < 2; ks++) {
            uint32_t af[4][4], bf[2][4];
#pragma unroll
            for (int mi = 0; mi < 4; mi++)
                ldsm_x4(af[mi], sA + (m_warp + 16 * mi) * 80 + ks * 32 + aoff);
#pragma unroll
            for (int j2 = 0; j2 < 2; j2++)
                ldsm_x4(bf[j2], sB + (n_warp + 16 * j2) * 80 + ks * 32 + boff);
#pragma unroll
            for (int mi = 0; mi < 4; mi++)
#pragma unroll
                for (int nj = 0; nj < 4; nj++)
                    mma_bf16(acc[mi][nj], af[mi], &bf[nj >> 1][(nj & 1) * 2]);
        }
        __syncthreads();
    }

#pragma unroll
    for (int mi = 0; mi < 4; mi++) {
        const int r0 = m0 + m_warp + 16 * mi + (lane >> 2);
#pragma unroll
        for (int nj = 0; nj < 4; nj++) {
            const int c = n0 + n_warp + 8 * nj + (lane & 3) * 2;
            float2 bv = *(const float2*)(bias + c);
            float2 o0 = make_float2(acc[mi][nj][0] + bv.x, acc[mi][nj][1] + bv.y);
            float2 o1 = make_float2(acc[mi][nj][2] + bv.x, acc[mi][nj][3] + bv.y);
            *(float2*)(Z + (size_t)r0 * ZC_ + c) = o0;
            *(float2*)(Z + (size_t)(r0 + 8) * ZC_ + c) = o1;
        }
    }
}

// ---------------------------------------------------------------------------
// Phase 2: persistent recurrence on HMMA (R12 layout) with:
//  - leaderless monotonic-counter group barrier (red.add.release + ld.acquire)
//  - weight-hi fragments preloaded into registers (W smem is static)
//  - batched staging LDGs (MLP 4) before STS
// ---------------------------------------------------------------------------
#define WROW   2064
#define AROW   1040
#define SM_W   (64 * WROW)
#define SM_AHH SM_W
#define SM_AHL (SM_W + 16640)
#define SM_R   (SM_W + 2 * 16640)
#define RK_SMEM (SM_R + 4 * 64 * 17 * 4)

__global__ __launch_bounds__(RK_THR, 1) void lstm_rec(
        const float* __restrict__ Wh,
        const float* __restrict__ h0l,
        const float* __restrict__ c0l,
        float* __restrict__ hseq,
        float* __restrict__ hs_out,
        float* __restrict__ cs_out) {
    extern __shared__ char smem[];
    const uint32_t sb = smem_u32(smem);
    float* Rsm = (float*)(smem + SM_R);

    const int tid  = threadIdx.x;
    const int cid  = blockIdx.x;
    const int grp  = cid & 3;
    const int cb   = cid >> 2;
    const int wid  = tid >> 5, lane = tid & 31;
    const int ks   = wid >> 2;
    const int nw   = wid & 3;

    unsigned* bcnt = &g_bcnt[grp * 32];
    unsigned* bgen = &g_bgen[grp * 32];
    unsigned* mono = &g_mono[grp * 32];

    // Read monotonic base BEFORE the init rendezvous (no arrivals can race it).
    unsigned mbase = 0;
    if (tid == 0) mbase = *mono;

    // Build W smem: row c (= hcol*4 + gate): [Wh | Wl] bf16
    for (int idx = tid; idx < 64 * 512; idx += RK_THR) {
        int c = idx >> 9, k = idx & 511;
        int hcol = c >> 2, gate = c & 3;
        float x = Wh[(size_t)k * ZC_ + (size_t)gate * HC_ + cb * 16 + hcol];
        __nv_bfloat16 h = __float2bfloat16(x);
        __nv_bfloat16 l = __float2bfloat16(x - __bfloat162float(h));
        *(__nv_bfloat16*)(smem + c * WROW + k * 2)        = h;
        *(__nv_bfloat16*)(smem + c * WROW + 1024 + k * 2) = l;
    }

    const uint32_t aoff = ((lane & 15) * 520 + (lane >> 4) * 8) * 2;
    const uint32_t boff = ((((lane >> 4) & 1) * 8 + (lane & 7)) * 1032
                           + ((lane >> 3) & 1) * 8) * 2;
    const uint32_t sBrow = sb + nw * 16 * WROW;

    // Finalizer identity
    const int fcol = tid & 15;
    const int fb   = tid >> 4;
    const int hcg  = cb * 16 + fcol;
    const int B    = grp * 16 + fb;
    float cstate = 0.f, hlast = 0.f;
    if (tid < 256) {
        cstate = c0l[hcg];
        hlast  = h0l[hcg];
        __nv_bfloat16 hh = __float2bfloat16(hlast);
        __nv_bfloat16 hl = __float2bfloat16(hlast - __bfloat162float(hh));
        g_hbf[0][grp][0][fb][hcg] = hh;
        g_hbf[0][grp][1][fb][hcg] = hl;
    }
    __syncthreads();
    // Init rendezvous (leader/gen protocol — one-time; also fences mbase reads)
    if (tid == 0) {
        unsigned gen = *bgen;
        unsigned old = atom_add_acqrel(bcnt, 1u);
        if (old == GCTAS - 1) { *bcnt = 0; st_release(bgen, gen + 1); }
        else { while (ld_acquire(bgen) == gen) {} }
    }
    __syncthreads();

    // Preload weight-hi fragments (static for the whole kernel): 32 regs
    uint32_t bhReg[8][4];
#pragma unroll
    for (int k8 = 0; k8 < 8; k8++)
        ldsm_x4(bhReg[k8], sBrow + (ks * 8 + k8) * 32 + boff);

    for (int t = 0; t < TT; t++) {
        // z prefetch (finalizers; consumed after GEMM)
        float z0 = 0.f, z1 = 0.f, z2 = 0.f, z3 = 0.f;
        if (tid < 256) {
            const float* zr = g_z + (size_t)(t * BSZ + B) * ZC_ + hcg;
            z0 = __ldcg(zr);
            z1 = __ldcg(zr + HC_);
            z2 = __ldcg(zr + 2 * HC_);
            z3 = __ldcg(zr + 3 * HC_);
        }

        // Stage h tile (32 KB): batch all 4 LDGs (MLP 4), then STS
        {
            const __nv_bfloat16* hsrc = &g_hbf[t & 1][grp][0][0][0];
            ulonglong2 v[4];
            int part[4], row[4], off[4];
#pragma unroll
            for (int j = 0; j < 4; j++) {
                int c = tid + j * 512;
                part[j] = c >> 10;
                int rem = c & 1023;
                row[j] = rem >> 6;
                off[j] = rem & 63;
                v[j] = __ldcg((const ulonglong2*)
                    (hsrc + (size_t)part[j] * 8192 + row[j] * 512 + off[j] * 8));
            }
#pragma unroll
            for (int j = 0; j < 4; j++)
                *(ulonglong2*)(smem + SM_AHH + part[j] * 16640 + row[j] * AROW
                               + off[j] * 16) = v[j];
        }
        __syncthreads();

        // GEMM: acc = hh*Wh + hl*Wh + hh*Wl over this warp's k-slice
        float acc[2][4];
#pragma unroll
        for (int nt = 0; nt < 2; nt++)
#pragma unroll
            for (int q = 0; q < 4; q++) acc[nt][q] = 0.f;

#pragma unroll
        for (int k8 = 0; k8 < 8; k8++) {
            const int kt = ks * 8 + k8;
            uint32_t ahh[4], ahl[4], bl[4];
            ldsm_x4(ahh, sb + SM_AHH + kt * 32 + aoff);
            ldsm_x4(ahl, sb + SM_AHL + kt * 32 + aoff);
            ldsm_x4(bl, sBrow + 1024 + kt * 32 + boff);
            mma_bf16(acc[0], ahh, &bhReg[k8][0]);
            mma_bf16(acc[1], ahh, &bhReg[k8][2]);
            mma_bf16(acc[0], ahl, &bhReg[k8][0]);
            mma_bf16(acc[1], ahl, &bhReg[k8][2]);
            mma_bf16(acc[0], ahh, &bl[0]);
            mma_bf16(acc[1], ahh, &bl[2]);
        }

        // Store partials: Rsm[(ks*64 + gc)*17 + b]
#pragma unroll
        for (int nt = 0; nt < 2; nt++) {
            int gc = nw * 16 + nt * 8 + (lane & 3) * 2;
            int b = lane >> 2;
            float* base = Rsm + (ks * 64 + gc) * 17;
            base[b]          = acc[nt][0];
            base[17 + b]     = acc[nt][1];
            base[b + 8]      = acc[nt][2];
            base[17 + b + 8] = acc[nt][3];
        }
        __syncthreads();

        // Finalize: 4-way k-reduce, gates, state update
        if (tid < 256) {
            float f = z0, i = z1, o = z2, g = z3;
#pragma unroll
            for (int q = 0; q < 4; q++) {
                const float* r = Rsm + (q * 64 + fcol * 4) * 17 + fb;
                f += r[0];
                i += r[17];
                o += r[34];
                g += r[51];
            }
            f = sigf(f + 1.0f);
            i = sigf(i);
            o = sigf(o);
            g = tanh_fast(g);
            cstate = cstate * f + g * i;
            hlast = o * tanh_fast(cstate);

            __nv_bfloat16 hh = __float2bfloat16(hlast);
            __nv_bfloat16 hl = __float2bfloat16(hlast - __bfloat162float(hh));
            g_hbf[(t + 1) & 1][grp][0][fb][hcg] = hh;
            g_hbf[(t + 1) & 1][grp][1][fb][hcg] = hl;
        }

        // Leaderless barrier: arrive, fold hseq store into the wait window, poll
        __syncthreads();                          // h stores done CTA-wide
        if (tid == 0) red_add_release(mono, 1u);
        if (tid < 256)
            hseq[(size_t)(t * BSZ + B) * HC_ + hcg] = hlast;
        if (tid == 0) {
            const unsigned tgt = mbase + (unsigned)GCTAS * (unsigned)(t + 1);
            while ((int)(ld_acquire(mono) - tgt) < 0) {}
        }
        __syncthreads();
    }

    if (tid < 256) {
        hs_out[B * HC_ + hcg] = hlast;
        cs_out[B * HC_ + hcg] = cstate;
    }
}

// ---------------------------------------------------------------------------
// Launch
// ---------------------------------------------------------------------------
extern "C" void kernel_launch(void* const* d_in, const int* in_sizes, int n_in,
                              void* d_out, int out_size) {
    const float* x  = (const float*)d_in[0];
    const float* W0 = (const float*)d_in[1];
    const float* b0 = (const float*)d_in[2];
    const float* W1 = (const float*)d_in[3];
    const float* b1 = (const float*)d_in[4];
    const float* h0 = (const float*)d_in[5];
    const float* c0 = (const float*)d_in[6];

    float* out = (float*)d_out;
    float* hs  = out + (size_t)TT * BSZ * HC_;
    float* cs  = hs + (size_t)2 * BSZ * HC_;

    float *zptr = nullptr, *hseq0 = nullptr;
    __nv_bfloat16 *abig = nullptr, *bbig = nullptr;
    cudaGetSymbolAddress((void**)&zptr, g_z);
    cudaGetSymbolAddress((void**)&hseq0, g_hseq);
    cudaGetSymbolAddress((void**)&abig, gAbig);
    cudaGetSymbolAddress((void**)&bbig, gBbig);

    static int attr_set = 0;
    if (!attr_set) {
        cudaFuncSetAttribute(lstm_rec, cudaFuncAttributeMaxDynamicSharedMemorySize, RK_SMEM);
        cudaFuncSetAttribute(sgemm_tc, cudaFuncAttributeMaxDynamicSharedMemorySize, TCSMEM);
        attr_set = 1;
    }

    dim3 tgrid(ZC_ / 128, MR / 128);

    // Layer 0
    conv_w<<<(512 * ZC_) / 256, 256>>>(W0, bbig);
    conv_a<<<(MR * IC_) / 1024, 256>>>(x, abig);
    sgemm_tc<<<tgrid, 256, TCSMEM>>>(abig, bbig, b0, zptr);
    lstm_rec<<<RK_CTAS, RK_THR, RK_SMEM>>>(W0 + (size_t)IC_ * ZC_, h0, c0,
                                           hseq0, hs, cs);
    // Layer 1
    conv_w<<<(512 * ZC_) / 256, 256>>>(W1, bbig);
    conv_a<<<(MR * HC_) / 1024, 256>>>(hseq0, abig);
    sgemm_tc<<<tgrid, 256, TCSMEM>>>(abig, bbig, b1, zptr);
    lstm_rec<<<RK_CTAS, RK_THR, RK_SMEM>>>(W1 + (size_t)HC_ * ZC_, h0 + HC_, c0 + HC_,
                                           out, hs + BSZ * HC_, cs + BSZ * HC_);
}

// round 14
// speedup vs baseline: 3.2477x; 1.0194x over previous
#include <cuda_runtime.h>
#include <cuda_bf16.h>
#include <cstdint>
#include <cstddef>

// Problem constants
#define TT   512
#define BSZ  64
#define IC_  512
#define HC_  512
#define ZC_  2048
#define MR   (TT*BSZ)
#define KBIG 1536

#define RK_CTAS 128
#define RK_THR  512
#define NGRP    4
#define GCTAS   32

typedef unsigned long long ull;

// ---------------------------------------------------------------------------
// Static device scratch
// ---------------------------------------------------------------------------
__device__ float g_z[(size_t)MR * ZC_];              // 256 MB
__device__ float g_hseq[(size_t)MR * HC_];           // 64 MB
__device__ __nv_bfloat16 g_hbf[2][NGRP][2][16][HC_]; // h as bf16 hi/lo, [b][k]
__device__ unsigned g_bcnt[NGRP * 32];               // init-rendezvous counters
__device__ unsigned g_bgen[NGRP * 32];
__device__ unsigned g_mono[NGRP * 32];               // monotonic step counters
__device__ __nv_bfloat16 gAbig[(size_t)MR * KBIG];   // 96 MB: [Ah | Ah | Al]
__device__ __nv_bfloat16 gBbig[(size_t)ZC_ * KBIG];  // 6 MB:  [Wh | Wl | Wh]

// ---------------------------------------------------------------------------
// Helpers
// ---------------------------------------------------------------------------
__device__ __forceinline__ unsigned atom_add_acqrel(unsigned* p, unsigned v) {
    unsigned old;
    asm volatile("atom.global.add.acq_rel.gpu.u32 %0, [%1], %2;"
                 : "=r"(old) : "l"(p), "r"(v) : "memory");
    return old;
}
__device__ __forceinline__ void red_add_release(unsigned* p, unsigned v) {
    asm volatile("red.global.add.release.gpu.u32 [%0], %1;" :: "l"(p), "r"(v) : "memory");
}
__device__ __forceinline__ unsigned ld_acquire(const unsigned* p) {
    unsigned v;
    asm volatile("ld.global.acquire.gpu.u32 %0, [%1];" : "=r"(v) : "l"(p) : "memory");
    return v;
}
__device__ __forceinline__ void st_release(unsigned* p, unsigned v) {
    asm volatile("st.global.release.gpu.u32 [%0], %1;" :: "l"(p), "r"(v) : "memory");
}
__device__ __forceinline__ float sigf(float x) { return 1.0f / (1.0f + __expf(-x)); }
__device__ __forceinline__ float tanh_fast(float x) {
    float ax = fabsf(x);
    float e = __expf(-2.0f * ax);
    float r = (1.0f - e) / (1.0f + e);
    return copysignf(r, x);
}
__device__ __forceinline__ uint32_t smem_u32(const void* p) {
    uint32_t a;
    asm("{ .reg .u64 t; cvta.to.shared.u64 t, %1; cvt.u32.u64 %0, t; }" : "=r"(a) : "l"(p));
    return a;
}
__device__ __forceinline__ void ldsm_x4(uint32_t* r, uint32_t addr) {
    asm volatile("ldmatrix.sync.aligned.m8n8.x4.shared.b16 {%0,%1,%2,%3}, [%4];"
                 : "=r"(r[0]), "=r"(r[1]), "=r"(r[2]), "=r"(r[3]) : "r"(addr));
}
__device__ __forceinline__ void mma_bf16(float* d, const uint32_t* a, const uint32_t* b) {
    asm volatile(
        "mma.sync.aligned.m16n8k16.row.col.f32.bf16.bf16.f32 "
        "{%0,%1,%2,%3}, {%4,%5,%6,%7}, {%8,%9}, {%0,%1,%2,%3};"
        : "+f"(d[0]), "+f"(d[1]), "+f"(d[2]), "+f"(d[3])
        : "r"(a[0]), "r"(a[1]), "r"(a[2]), "r"(a[3]), "r"(b[0]), "r"(b[1]));
}

// ---------------------------------------------------------------------------
// Conversion kernels (R11-exact)
// ---------------------------------------------------------------------------
__global__ __launch_bounds__(256) void conv_a(
        const float* __restrict__ A, __nv_bfloat16* __restrict__ Abig) {
    size_t i = ((size_t)blockIdx.x * 256 + threadIdx.x) * 4;
    int m = (int)(i >> 9), k = (int)(i & 511);
    float4 v = *(const float4*)(A + i);
    __nv_bfloat16 h[4], l[4];
    const float* vf = (const float*)&v;
#pragma unroll
    for (int q = 0; q < 4; q++) {
        h[q] = __float2bfloat16(vf[q]);
        l[q] = __float2bfloat16(vf[q] - __bfloat162float(h[q]));
    }
    __nv_bfloat16* row = Abig + (size_t)m * KBIG;
    *(ull*)(row + k)        = *(const ull*)h;
    *(ull*)(row + 512 + k)  = *(const ull*)h;
    *(ull*)(row + 1024 + k) = *(const ull*)l;
}

__global__ __launch_bounds__(256) void conv_w(
        const float* __restrict__ W, __nv_bfloat16* __restrict__ Bbig) {
    int idx = blockIdx.x * 256 + threadIdx.x;
    int k = idx >> 11, n = idx & 2047;
    float x = W[idx];
    __nv_bfloat16 h = __float2bfloat16(x);
    __nv_bfloat16 l = __float2bfloat16(x - __bfloat162float(h));
    __nv_bfloat16* row = Bbig + (size_t)n * KBIG;
    row[k]        = h;
    row[512 + k]  = l;
    row[1024 + k] = h;
}

// ---------------------------------------------------------------------------
// Phase 1: HMMA GEMM (R11/R12-exact)
// ---------------------------------------------------------------------------
#define ROWB 40
#define AS_BYTES (128 * ROWB * 2)
#define STAGE_BYTES (2 * AS_BYTES)
#define TCSMEM (2 * STAGE_BYTES)

__global__ __launch_bounds__(256, 2) void sgemm_tc(
        const __nv_bfloat16* __restrict__ Abig,
        const __nv_bfloat16* __restrict__ Bbig,
        const float* __restrict__ bias,
        float* __restrict__ Z) {
    extern __shared__ char smem[];
    const uint32_t sbase = smem_u32(smem);
    const int tid = threadIdx.x;
    const int wid = tid >> 5, lane = tid & 31;
    const int m0 = blockIdx.y * 128;
    const int n0 = blockIdx.x * 128;
    const int m_warp = (wid & 1) * 64;
    const int n_warp = (wid >> 1) * 32;

    float acc[4][4][4];
#pragma unroll
    for (int i = 0; i < 4; i++)
#pragma unroll
        for (int j = 0; j < 4; j++)
#pragma unroll
            for (int q = 0; q < 4; q++) acc[i][j][q] = 0.f;

    const int c0 = tid * 2;
    const int arow0 = c0 >> 2,       acol0 = (c0 & 3) * 8;
    const int arow1 = (c0 + 1) >> 2, acol1 = ((c0 + 1) & 3) * 8;

    const uint32_t aoff = ((lane & 15) * ROWB + (lane >> 4) * 8) * 2;
    const uint32_t boff = ((((lane >> 4) & 1) * 8 + (lane & 7)) * ROWB
                           + ((lane >> 3) & 1) * 8) * 2;

    ulonglong2 aPf0, aPf1, bPf0, bPf1;
    aPf0 = *(const ulonglong2*)(Abig + (size_t)(m0 + arow0) * KBIG + acol0);
    aPf1 = *(const ulonglong2*)(Abig + (size_t)(m0 + arow1) * KBIG + acol1);
    bPf0 = *(const ulonglong2*)(Bbig + (size_t)(n0 + arow0) * KBIG + acol0);
    bPf1 = *(const ulonglong2*)(Bbig + (size_t)(n0 + arow1) * KBIG + acol1);

    for (int it = 0; it < KBIG / 32; it++) {
        const int s = it & 1;
        char* As = smem + s * STAGE_BYTES;
        char* Bs = As + AS_BYTES;

        *(ulonglong2*)(As + arow0 * 80 + acol0 * 2) = aPf0;
        *(ulonglong2*)(As + arow1 * 80 + acol1 * 2) = aPf1;
        *(ulonglong2*)(Bs + arow0 * 80 + acol0 * 2) = bPf0;
        *(ulonglong2*)(Bs + arow1 * 80 + acol1 * 2) = bPf1;
        __syncthreads();

        if (it + 1 < KBIG / 32) {
            const int kb = (it + 1) * 32;
            aPf0 = *(const ulonglong2*)(Abig + (size_t)(m0 + arow0) * KBIG + kb + acol0);
            aPf1 = *(const ulonglong2*)(Abig + (size_t)(m0 + arow1) * KBIG + kb + acol1);
            bPf0 = *(const ulonglong2*)(Bbig + (size_t)(n0 + arow0) * KBIG + kb + acol0);
            bPf1 = *(const ulonglong2*)(Bbig + (size_t)(n0 + arow1) * KBIG + kb + acol1);
        }

        const uint32_t sA = sbase + s * STAGE_BYTES;
        const uint32_t sB = sA + AS_BYTES;
#pragma unroll
        for (int ks = 0; ks < 2; ks++) {
            uint32_t af[4][4], bf[2][4];
#pragma unroll
            for (int mi = 0; mi < 4; mi++)
                ldsm_x4(af[mi], sA + (m_warp + 16 * mi) * 80 + ks * 32 + aoff);
#pragma unroll
            for (int j2 = 0; j2 < 2; j2++)
                ldsm_x4(bf[j2], sB + (n_warp + 16 * j2) * 80 + ks * 32 + boff);
#pragma unroll
            for (int mi = 0; mi < 4; mi++)
#pragma unroll
                for (int nj = 0; nj < 4; nj++)
                    mma_bf16(acc[mi][nj], af[mi], &bf[nj >> 1][(nj & 1) * 2]);
        }
        __syncthreads();
    }

#pragma unroll
    for (int mi = 0; mi < 4; mi++) {
        const int r0 = m0 + m_warp + 16 * mi + (lane >> 2);
#pragma unroll
        for (int nj = 0; nj < 4; nj++) {
            const int c = n0 + n_warp + 8 * nj + (lane & 3) * 2;
            float2 bv = *(const float2*)(bias + c);
            float2 o0 = make_float2(acc[mi][nj][0] + bv.x, acc[mi][nj][1] + bv.y);
            float2 o1 = make_float2(acc[mi][nj][2] + bv.x, acc[mi][nj][3] + bv.y);
            *(float2*)(Z + (size_t)r0 * ZC_ + c) = o0;
            *(float2*)(Z + (size_t)(r0 + 8) * ZC_ + c) = o1;
        }
    }
}

// ---------------------------------------------------------------------------
// Phase 2: persistent recurrence on HMMA (R13 layout) with:
//  - z loads software-pipelined one step ahead (DRAM latency off the chain)
//  - BOTH weight-hi and weight-lo fragments preloaded into registers
//  - leaderless monotonic barrier (R13-proven)
// ---------------------------------------------------------------------------
#define WROW   2064
#define AROW   1040
#define SM_W   (64 * WROW)
#define SM_AHH SM_W
#define SM_AHL (SM_W + 16640)
#define SM_R   (SM_W + 2 * 16640)
#define RK_SMEM (SM_R + 4 * 64 * 17 * 4)

__global__ __launch_bounds__(RK_THR, 1) void lstm_rec(
        const float* __restrict__ Wh,
        const float* __restrict__ h0l,
        const float* __restrict__ c0l,
        float* __restrict__ hseq,
        float* __restrict__ hs_out,
        float* __restrict__ cs_out) {
    extern __shared__ char smem[];
    const uint32_t sb = smem_u32(smem);
    float* Rsm = (float*)(smem + SM_R);

    const int tid  = threadIdx.x;
    const int cid  = blockIdx.x;
    const int grp  = cid & 3;
    const int cb   = cid >> 2;
    const int wid  = tid >> 5, lane = tid & 31;
    const int ks   = wid >> 2;
    const int nw   = wid & 3;

    unsigned* bcnt = &g_bcnt[grp * 32];
    unsigned* bgen = &g_bgen[grp * 32];
    unsigned* mono = &g_mono[grp * 32];

    // Read monotonic base BEFORE the init rendezvous (no arrivals can race it).
    unsigned mbase = 0;
    if (tid == 0) mbase = *mono;

    // Build W smem: row c (= hcol*4 + gate): [Wh | Wl] bf16
    for (int idx = tid; idx < 64 * 512; idx += RK_THR) {
        int c = idx >> 9, k = idx & 511;
        int hcol = c >> 2, gate = c & 3;
        float x = Wh[(size_t)k * ZC_ + (size_t)gate * HC_ + cb * 16 + hcol];
        __nv_bfloat16 h = __float2bfloat16(x);
        __nv_bfloat16 l = __float2bfloat16(x - __bfloat162float(h));
        *(__nv_bfloat16*)(smem + c * WROW + k * 2)        = h;
        *(__nv_bfloat16*)(smem + c * WROW + 1024 + k * 2) = l;
    }

    const uint32_t aoff = ((lane & 15) * 520 + (lane >> 4) * 8) * 2;
    const uint32_t boff = ((((lane >> 4) & 1) * 8 + (lane & 7)) * 1032
                           + ((lane >> 3) & 1) * 8) * 2;
    const uint32_t sBrow = sb + nw * 16 * WROW;

    // Finalizer identity
    const int fcol = tid & 15;
    const int fb   = tid >> 4;
    const int hcg  = cb * 16 + fcol;
    const int B    = grp * 16 + fb;
    const float* zbase = g_z + (size_t)B * ZC_ + hcg;
    float cstate = 0.f, hlast = 0.f;
    if (tid < 256) {
        cstate = c0l[hcg];
        hlast  = h0l[hcg];
        __nv_bfloat16 hh = __float2bfloat16(hlast);
        __nv_bfloat16 hl = __float2bfloat16(hlast - __bfloat162float(hh));
        g_hbf[0][grp][0][fb][hcg] = hh;
        g_hbf[0][grp][1][fb][hcg] = hl;
    }
    __syncthreads();
    // Init rendezvous (leader/gen protocol — one-time; also fences mbase reads)
    if (tid == 0) {
        unsigned gen = *bgen;
        unsigned old = atom_add_acqrel(bcnt, 1u);
        if (old == GCTAS - 1) { *bcnt = 0; st_release(bgen, gen + 1); }
        else { while (ld_acquire(bgen) == gen) {} }
    }
    __syncthreads();

    // Preload BOTH weight fragment sets (static for the whole kernel): 64 regs
    uint32_t bhReg[8][4], blReg[8][4];
#pragma unroll
    for (int k8 = 0; k8 < 8; k8++) {
        ldsm_x4(bhReg[k8], sBrow + (ks * 8 + k8) * 32 + boff);
        ldsm_x4(blReg[k8], sBrow + 1024 + (ks * 8 + k8) * 32 + boff);
    }

    // Prologue: z for step 0 (in flight while first h staging happens)
    float zc0 = 0.f, zc1 = 0.f, zc2 = 0.f, zc3 = 0.f;
    if (tid < 256) {
        zc0 = __ldcg(zbase);
        zc1 = __ldcg(zbase + HC_);
        zc2 = __ldcg(zbase + 2 * HC_);
        zc3 = __ldcg(zbase + 3 * HC_);
    }

    for (int t = 0; t < TT; t++) {
        // Stage h tile (32 KB): batch all 4 LDGs (MLP 4), then STS
        {
            const __nv_bfloat16* hsrc = &g_hbf[t & 1][grp][0][0][0];
            ulonglong2 v[4];
            int part[4], row[4], off[4];
#pragma unroll
            for (int j = 0; j < 4; j++) {
                int c = tid + j * 512;
                part[j] = c >> 10;
                int rem = c & 1023;
                row[j] = rem >> 6;
                off[j] = rem & 63;
                v[j] = __ldcg((const ulonglong2*)
                    (hsrc + (size_t)part[j] * 8192 + row[j] * 512 + off[j] * 8));
            }
#pragma unroll
            for (int j = 0; j < 4; j++)
                *(ulonglong2*)(smem + SM_AHH + part[j] * 16640 + row[j] * AROW
                               + off[j] * 16) = v[j];
        }
        __syncthreads();

        // Prefetch z for the NEXT step (covered by GEMM + reduce below)
        float zn0 = 0.f, zn1 = 0.f, zn2 = 0.f, zn3 = 0.f;
        if (tid < 256 && t + 1 < TT) {
            const float* zr = zbase + (size_t)(t + 1) * BSZ * ZC_;
            zn0 = __ldcg(zr);
            zn1 = __ldcg(zr + HC_);
            zn2 = __ldcg(zr + 2 * HC_);
            zn3 = __ldcg(zr + 3 * HC_);
        }

        // GEMM: acc = hh*Wh + hl*Wh + hh*Wl over this warp's k-slice
        float acc[2][4];
#pragma unroll
        for (int nt = 0; nt < 2; nt++)
#pragma unroll
            for (int q = 0; q < 4; q++) acc[nt][q] = 0.f;

#pragma unroll
        for (int k8 = 0; k8 < 8; k8++) {
            const int kt = ks * 8 + k8;
            uint32_t ahh[4], ahl[4];
            ldsm_x4(ahh, sb + SM_AHH + kt * 32 + aoff);
            ldsm_x4(ahl, sb + SM_AHL + kt * 32 + aoff);
            mma_bf16(acc[0], ahh, &bhReg[k8][0]);
            mma_bf16(acc[1], ahh, &bhReg[k8][2]);
            mma_bf16(acc[0], ahl, &bhReg[k8][0]);
            mma_bf16(acc[1], ahl, &bhReg[k8][2]);
            mma_bf16(acc[0], ahh, &blReg[k8][0]);
            mma_bf16(acc[1], ahh, &blReg[k8][2]);
        }

        // Store partials: Rsm[(ks*64 + gc)*17 + b]
#pragma unroll
        for (int nt = 0; nt < 2; nt++) {
            int gc = nw * 16 + nt * 8 + (lane & 3) * 2;
            int b = lane >> 2;
            float* base = Rsm + (ks * 64 + gc) * 17;
            base[b]          = acc[nt][0];
            base[17 + b]     = acc[nt][1];
            base[b + 8]      = acc[nt][2];
            base[17 + b + 8] = acc[nt][3];
        }
        __syncthreads();

        // Finalize: 4-way k-reduce, gates, state update (consumes current z)
        if (tid < 256) {
            float f = zc0, i = zc1, o = zc2, g = zc3;
#pragma unroll
            for (int q = 0; q < 4; q++) {
                const float* r = Rsm + (q * 64 + fcol * 4) * 17 + fb;
                f += r[0];
                i += r[17];
                o += r[34];
                g += r[51];
            }
            f = sigf(f + 1.0f);
            i = sigf(i);
            o = sigf(o);
            g = tanh_fast(g);
            cstate = cstate * f + g * i;
            hlast = o * tanh_fast(cstate);

            __nv_bfloat16 hh = __float2bfloat16(hlast);
            __nv_bfloat16 hl = __float2bfloat16(hlast - __bfloat162float(hh));
            g_hbf[(t + 1) & 1][grp][0][fb][hcg] = hh;
            g_hbf[(t + 1) & 1][grp][1][fb][hcg] = hl;
        }
        zc0 = zn0; zc1 = zn1; zc2 = zn2; zc3 = zn3;

        // Leaderless barrier: arrive, fold hseq store into the wait window, poll
        __syncthreads();                          // h stores done CTA-wide
        if (tid == 0) red_add_release(mono, 1u);
        if (tid < 256)
            hseq[(size_t)(t * BSZ + B) * HC_ + hcg] = hlast;
        if (tid == 0) {
            const unsigned tgt = mbase + (unsigned)GCTAS * (unsigned)(t + 1);
            while ((int)(ld_acquire(mono) - tgt) < 0) {}
        }
        __syncthreads();
    }

    if (tid < 256) {
        hs_out[B * HC_ + hcg] = hlast;
        cs_out[B * HC_ + hcg] = cstate;
    }
}

// ---------------------------------------------------------------------------
// Launch
// ---------------------------------------------------------------------------
extern "C" void kernel_launch(void* const* d_in, const int* in_sizes, int n_in,
                              void* d_out, int out_size) {
    const float* x  = (const float*)d_in[0];
    const float* W0 = (const float*)d_in[1];
    const float* b0 = (const float*)d_in[2];
    const float* W1 = (const float*)d_in[3];
    const float* b1 = (const float*)d_in[4];
    const float* h0 = (const float*)d_in[5];
    const float* c0 = (const float*)d_in[6];

    float* out = (float*)d_out;
    float* hs  = out + (size_t)TT * BSZ * HC_;
    float* cs  = hs + (size_t)2 * BSZ * HC_;

    float *zptr = nullptr, *hseq0 = nullptr;
    __nv_bfloat16 *abig = nullptr, *bbig = nullptr;
    cudaGetSymbolAddress((void**)&zptr, g_z);
    cudaGetSymbolAddress((void**)&hseq0, g_hseq);
    cudaGetSymbolAddress((void**)&abig, gAbig);
    cudaGetSymbolAddress((void**)&bbig, gBbig);

    static int attr_set = 0;
    if (!attr_set) {
        cudaFuncSetAttribute(lstm_rec, cudaFuncAttributeMaxDynamicSharedMemorySize, RK_SMEM);
        cudaFuncSetAttribute(sgemm_tc, cudaFuncAttributeMaxDynamicSharedMemorySize, TCSMEM);
        attr_set = 1;
    }

    dim3 tgrid(ZC_ / 128, MR / 128);

    // Layer 0
    conv_w<<<(512 * ZC_) / 256, 256>>>(W0, bbig);
    conv_a<<<(MR * IC_) / 1024, 256>>>(x, abig);
    sgemm_tc<<<tgrid, 256, TCSMEM>>>(abig, bbig, b0, zptr);
    lstm_rec<<<RK_CTAS, RK_THR, RK_SMEM>>>(W0 + (size_t)IC_ * ZC_, h0, c0,
                                           hseq0, hs, cs);
    // Layer 1
    conv_w<<<(512 * ZC_) / 256, 256>>>(W1, bbig);
    conv_a<<<(MR * HC_) / 1024, 256>>>(hseq0, abig);
    sgemm_tc<<<tgrid, 256, TCSMEM>>>(abig, bbig, b1, zptr);
    lstm_rec<<<RK_CTAS, RK_THR, RK_SMEM>>>(W1 + (size_t)HC_ * ZC_, h0 + HC_, c0 + HC_,
                                           out, hs + BSZ * HC_, cs + BSZ * HC_);
}